// round 1
// baseline (speedup 1.0000x reference)
#include <cuda_runtime.h>

// Problem constants
constexpr int Bb  = 2;
constexpr int Ss  = 2048;
constexpr int Dd  = 1024;
constexpr int Hh  = 16;
constexpr int HD  = 64;
constexpr int Mm  = Bb * Ss;   // 4096 rows for all GEMMs

// Scratch (allocation-free rule: __device__ globals)
__device__ float g_Q[Bb * Hh * Ss * HD];    // [B,H,S,HD]
__device__ float g_K[Bb * Hh * Ss * HD];
__device__ float g_V[Bb * Hh * Ss * HD];
__device__ float g_ctx[Bb * Ss * Dd];       // [B,S,D]

// ---------------------------------------------------------------------------
// 128x128x8 SGEMM (NT: both operands K-major / row-major with K contiguous)
//   y[m,n] = sum_k A[m,k] * W[n,k]
// MODE 0: QKV projection — blockIdx.z selects Wq/Wk/Wv, writes [B,H,S,HD]
// MODE 1: output projection — A = g_ctx, adds bias, writes d_out [B,S,D]
// ---------------------------------------------------------------------------
template <int MODE>
__global__ __launch_bounds__(256) void gemm128(const float* __restrict__ A,
                                               const float* __restrict__ W0,
                                               const float* __restrict__ W1,
                                               const float* __restrict__ W2,
                                               const float* __restrict__ bias,
                                               float* __restrict__ out_direct)
{
    __shared__ float As[8][128];
    __shared__ float Bs[8][128];

    const float* Ain;
    const float* Wsel;
    float* obuf;
    if (MODE == 0) {
        Ain  = A;
        Wsel = (blockIdx.z == 0) ? W0 : (blockIdx.z == 1 ? W1 : W2);
        obuf = (blockIdx.z == 0) ? g_Q : (blockIdx.z == 1 ? g_K : g_V);
    } else {
        Ain  = g_ctx;
        Wsel = W0;
        obuf = out_direct;
    }

    const int tid  = threadIdx.x;
    const int tx   = tid & 15;
    const int ty   = tid >> 4;
    const int m0   = blockIdx.y * 128;
    const int n0   = blockIdx.x * 128;
    const int lrow = tid >> 1;
    const int lhalf = tid & 1;

    const float* Arow = Ain  + (size_t)(m0 + lrow) * Dd + lhalf * 4;
    const float* Wrow = Wsel + (size_t)(n0 + lrow) * Dd + lhalf * 4;

    float acc[8][8];
#pragma unroll
    for (int i = 0; i < 8; i++)
#pragma unroll
        for (int j = 0; j < 8; j++) acc[i][j] = 0.0f;

    for (int k0 = 0; k0 < Dd; k0 += 8) {
        float4 av = *(const float4*)(Arow + k0);
        float4 bv = *(const float4*)(Wrow + k0);
        __syncthreads();  // previous-iteration compute must finish before overwrite
        As[lhalf * 4 + 0][lrow] = av.x;
        As[lhalf * 4 + 1][lrow] = av.y;
        As[lhalf * 4 + 2][lrow] = av.z;
        As[lhalf * 4 + 3][lrow] = av.w;
        Bs[lhalf * 4 + 0][lrow] = bv.x;
        Bs[lhalf * 4 + 1][lrow] = bv.y;
        Bs[lhalf * 4 + 2][lrow] = bv.z;
        Bs[lhalf * 4 + 3][lrow] = bv.w;
        __syncthreads();
#pragma unroll
        for (int kk = 0; kk < 8; kk++) {
            float4 a0 = *(const float4*)&As[kk][ty * 8];
            float4 a1 = *(const float4*)&As[kk][ty * 8 + 4];
            float4 b0 = *(const float4*)&Bs[kk][tx * 8];
            float4 b1 = *(const float4*)&Bs[kk][tx * 8 + 4];
            float a[8] = {a0.x, a0.y, a0.z, a0.w, a1.x, a1.y, a1.z, a1.w};
            float b[8] = {b0.x, b0.y, b0.z, b0.w, b1.x, b1.y, b1.z, b1.w};
#pragma unroll
            for (int i = 0; i < 8; i++)
#pragma unroll
                for (int j = 0; j < 8; j++) acc[i][j] += a[i] * b[j];
        }
    }

    if (MODE == 0) {
        // scatter into [B,H,S,HD]
#pragma unroll
        for (int i = 0; i < 8; i++) {
            int m = m0 + ty * 8 + i;
            int b = m >> 11;          // m / 2048
            int s = m & 2047;
#pragma unroll
            for (int j = 0; j < 8; j++) {
                int n = n0 + tx * 8 + j;
                int h = n >> 6;
                int d = n & 63;
                obuf[(((size_t)(b * Hh + h)) * Ss + s) * HD + d] = acc[i][j];
            }
        }
    } else {
#pragma unroll
        for (int i = 0; i < 8; i++) {
            int m = m0 + ty * 8 + i;
            float* dst = obuf + (size_t)m * Dd + n0 + tx * 8;
            float4 o0, o1;
            o0.x = acc[i][0] + bias[n0 + tx * 8 + 0];
            o0.y = acc[i][1] + bias[n0 + tx * 8 + 1];
            o0.z = acc[i][2] + bias[n0 + tx * 8 + 2];
            o0.w = acc[i][3] + bias[n0 + tx * 8 + 3];
            o1.x = acc[i][4] + bias[n0 + tx * 8 + 4];
            o1.y = acc[i][5] + bias[n0 + tx * 8 + 5];
            o1.z = acc[i][6] + bias[n0 + tx * 8 + 6];
            o1.w = acc[i][7] + bias[n0 + tx * 8 + 7];
            *(float4*)(dst)     = o0;
            *(float4*)(dst + 4) = o1;
        }
    }
}

// ---------------------------------------------------------------------------
// Causal flash attention, fp32.
// Grid: (S/64, B*H). Block: 256 threads, 4x4 microtile over a 64x64 tile.
// smem (dynamic, 69.6 KB): Qs[d][i], Ks[d][j] (transposed), Vs[k][d], Ps[i][k]
// ---------------------------------------------------------------------------
constexpr int ATT_STRIDE = 68;                     // 64 + pad, float4-aligned
constexpr int ATT_SMEM   = 4 * 64 * ATT_STRIDE * 4;  // bytes

__global__ __launch_bounds__(256) void flash_attn()
{
    extern __shared__ float sm[];
    float* Qs = sm;                      // [64][68]  (d-major: Qs[d][i])
    float* Ks = sm + 64 * ATT_STRIDE;    // [64][68]  (d-major: Ks[d][j])
    float* Vs = sm + 2 * 64 * ATT_STRIDE;// [64][68]  (k-major: Vs[k][dv])
    float* Ps = sm + 3 * 64 * ATT_STRIDE;// [64][68]  (i-major: Ps[i][k])

    const int tid = threadIdx.x;
    const int tx  = tid & 15;
    const int ty  = tid >> 4;
    const int qt  = blockIdx.x;
    const int bh  = blockIdx.y;

    const float* Qb = g_Q + (size_t)bh * Ss * HD;
    const float* Kb = g_K + (size_t)bh * Ss * HD;
    const float* Vb = g_V + (size_t)bh * Ss * HD;

    // Load Q tile (transposed into [d][i])
#pragma unroll
    for (int it = 0; it < 4; it++) {
        int idx = tid + it * 256;
        int row = idx >> 4;
        int q4  = idx & 15;
        float4 v = *(const float4*)&Qb[(size_t)(qt * 64 + row) * HD + q4 * 4];
        Qs[(q4 * 4 + 0) * ATT_STRIDE + row] = v.x;
        Qs[(q4 * 4 + 1) * ATT_STRIDE + row] = v.y;
        Qs[(q4 * 4 + 2) * ATT_STRIDE + row] = v.z;
        Qs[(q4 * 4 + 3) * ATT_STRIDE + row] = v.w;
    }

    float m_i[4], l_i[4], o[4][4];
#pragma unroll
    for (int i = 0; i < 4; i++) {
        m_i[i] = -1e30f;
        l_i[i] = 0.0f;
#pragma unroll
        for (int j = 0; j < 4; j++) o[i][j] = 0.0f;
    }

    for (int kt = 0; kt <= qt; kt++) {
        __syncthreads();  // prior PV reads of Vs done before overwrite
#pragma unroll
        for (int it = 0; it < 4; it++) {
            int idx = tid + it * 256;
            int row = idx >> 4;
            int q4  = idx & 15;
            float4 kv = *(const float4*)&Kb[(size_t)(kt * 64 + row) * HD + q4 * 4];
            Ks[(q4 * 4 + 0) * ATT_STRIDE + row] = kv.x;
            Ks[(q4 * 4 + 1) * ATT_STRIDE + row] = kv.y;
            Ks[(q4 * 4 + 2) * ATT_STRIDE + row] = kv.z;
            Ks[(q4 * 4 + 3) * ATT_STRIDE + row] = kv.w;
            float4 vv = *(const float4*)&Vb[(size_t)(kt * 64 + row) * HD + q4 * 4];
            *(float4*)&Vs[row * ATT_STRIDE + q4 * 4] = vv;
        }
        __syncthreads();

        // S = Q K^T
        float sc[4][4];
#pragma unroll
        for (int i = 0; i < 4; i++)
#pragma unroll
            for (int j = 0; j < 4; j++) sc[i][j] = 0.0f;

#pragma unroll 16
        for (int d = 0; d < 64; d++) {
            float4 aq = *(const float4*)&Qs[d * ATT_STRIDE + ty * 4];
            float4 bk = *(const float4*)&Ks[d * ATT_STRIDE + tx * 4];
            float a[4] = {aq.x, aq.y, aq.z, aq.w};
            float b[4] = {bk.x, bk.y, bk.z, bk.w};
#pragma unroll
            for (int i = 0; i < 4; i++)
#pragma unroll
                for (int j = 0; j < 4; j++) sc[i][j] += a[i] * b[j];
        }

        const bool diag = (kt == qt);
#pragma unroll
        for (int i = 0; i < 4; i++)
#pragma unroll
            for (int j = 0; j < 4; j++) {
                float v = sc[i][j] * 0.125f;  // 1/sqrt(64)
                if (diag && (tx * 4 + j) > (ty * 4 + i)) v = -1e30f;
                sc[i][j] = v;
            }

        // online softmax per row (row group = 16 lanes sharing ty → shfl width 16)
#pragma unroll
        for (int i = 0; i < 4; i++) {
            float mx = fmaxf(fmaxf(sc[i][0], sc[i][1]), fmaxf(sc[i][2], sc[i][3]));
#pragma unroll
            for (int off = 8; off; off >>= 1)
                mx = fmaxf(mx, __shfl_xor_sync(0xffffffffu, mx, off));
            float nm = fmaxf(m_i[i], mx);
            float sum = 0.0f;
#pragma unroll
            for (int j = 0; j < 4; j++) {
                float p = __expf(sc[i][j] - nm);
                sc[i][j] = p;
                sum += p;
            }
#pragma unroll
            for (int off = 8; off; off >>= 1)
                sum += __shfl_xor_sync(0xffffffffu, sum, off);
            float alpha = __expf(m_i[i] - nm);
            m_i[i] = nm;
            l_i[i] = l_i[i] * alpha + sum;
#pragma unroll
            for (int j = 0; j < 4; j++) o[i][j] *= alpha;
#pragma unroll
            for (int j = 0; j < 4; j++)
                Ps[(ty * 4 + i) * ATT_STRIDE + tx * 4 + j] = sc[i][j];
        }
        __syncwarp();  // P rows this thread reads are written within its own warp

        // O += P V
#pragma unroll 8
        for (int k = 0; k < 64; k++) {
            float4 vv = *(const float4*)&Vs[k * ATT_STRIDE + tx * 4];
#pragma unroll
            for (int i = 0; i < 4; i++) {
                float p = Ps[(ty * 4 + i) * ATT_STRIDE + k];
                o[i][0] += p * vv.x;
                o[i][1] += p * vv.y;
                o[i][2] += p * vv.z;
                o[i][3] += p * vv.w;
            }
        }
    }

    // normalize and write ctx [B,S,D]
    const int b = bh >> 4;
    const int h = bh & 15;
#pragma unroll
    for (int i = 0; i < 4; i++) {
        float inv = 1.0f / l_i[i];
        int srow = qt * 64 + ty * 4 + i;
        float4 ov;
        ov.x = o[i][0] * inv;
        ov.y = o[i][1] * inv;
        ov.z = o[i][2] * inv;
        ov.w = o[i][3] * inv;
        *(float4*)&g_ctx[((size_t)(b * Ss + srow)) * Dd + h * HD + tx * 4] = ov;
    }
}

// ---------------------------------------------------------------------------
extern "C" void kernel_launch(void* const* d_in, const int* in_sizes, int n_in,
                              void* d_out, int out_size)
{
    const float* x  = (const float*)d_in[0];
    const float* Wq = (const float*)d_in[1];
    const float* Wk = (const float*)d_in[2];
    const float* Wv = (const float*)d_in[3];
    const float* Wo = (const float*)d_in[4];
    const float* bo = (const float*)d_in[5];
    float* out = (float*)d_out;

    cudaFuncSetAttribute(flash_attn, cudaFuncAttributeMaxDynamicSharedMemorySize,
                         ATT_SMEM);

    // QKV projections: grid (N/128, M/128, 3)
    gemm128<0><<<dim3(Dd / 128, Mm / 128, 3), 256>>>(x, Wq, Wk, Wv, nullptr, nullptr);

    // Causal flash attention: grid (S/64, B*H)
    flash_attn<<<dim3(Ss / 64, Bb * Hh), 256, ATT_SMEM>>>();

    // Output projection + bias
    gemm128<1><<<dim3(Dd / 128, Mm / 128, 1), 256>>>(nullptr, Wo, nullptr, nullptr, bo, out);
}

// round 4
// speedup vs baseline: 2.5634x; 2.5634x over previous
#include <cuda_runtime.h>
#include <cuda_bf16.h>
#include <cstdint>

constexpr int Bb = 2, Ss = 2048, Dd = 1024, Hh = 16, HD = 64;
constexpr int Mm = Bb * Ss;  // 4096

// bf16 hi/lo split scratch (allocation-free rule: __device__ globals)
__device__ __nv_bfloat16 g_xh[Mm * Dd],  g_xl[Mm * Dd];
__device__ __nv_bfloat16 g_Wh[4 * Dd * Dd], g_Wl[4 * Dd * Dd];
__device__ __nv_bfloat16 g_Qh[Mm * Dd],  g_Ql[Mm * Dd];   // [B,H,S,HD]
__device__ __nv_bfloat16 g_Kh[Mm * Dd],  g_Kl[Mm * Dd];
__device__ __nv_bfloat16 g_Vh[Mm * Dd],  g_Vl[Mm * Dd];
__device__ __nv_bfloat16 g_ctxh[Mm * Dd], g_ctxl[Mm * Dd]; // [B*S, D]

// ---------------------------------------------------------------------------
// helpers
// ---------------------------------------------------------------------------
__device__ __forceinline__ uint32_t smaddr(const void* p) {
    uint32_t a;
    asm("{ .reg .u64 t; cvta.to.shared.u64 t, %1; cvt.u32.u64 %0, t; }"
        : "=r"(a) : "l"(p));
    return a;
}
__device__ __forceinline__ void ldsm4(uint32_t* r, uint32_t a) {
    asm volatile("ldmatrix.sync.aligned.m8n8.x4.shared.b16 {%0,%1,%2,%3}, [%4];"
                 : "=r"(r[0]), "=r"(r[1]), "=r"(r[2]), "=r"(r[3]) : "r"(a));
}
__device__ __forceinline__ void ldsm4t(uint32_t* r, uint32_t a) {
    asm volatile("ldmatrix.sync.aligned.m8n8.x4.trans.shared.b16 {%0,%1,%2,%3}, [%4];"
                 : "=r"(r[0]), "=r"(r[1]), "=r"(r[2]), "=r"(r[3]) : "r"(a));
}
__device__ __forceinline__ void mma16816(float* c, const uint32_t* a, const uint32_t* b) {
    asm volatile(
        "mma.sync.aligned.m16n8k16.row.col.f32.bf16.bf16.f32 "
        "{%0,%1,%2,%3}, {%4,%5,%6,%7}, {%8,%9}, {%0,%1,%2,%3};"
        : "+f"(c[0]), "+f"(c[1]), "+f"(c[2]), "+f"(c[3])
        : "r"(a[0]), "r"(a[1]), "r"(a[2]), "r"(a[3]), "r"(b[0]), "r"(b[1]));
}
__device__ __forceinline__ float ex2f(float x) {
    float y;
    asm("ex2.approx.ftz.f32 %0, %1;" : "=f"(y) : "f"(x));
    return y;
}
// fp32 -> (bf16 hi, bf16 lo) for two values, packed as bf16x2 words (low = first arg)
__device__ __forceinline__ void split2(float a, float b, uint32_t& h, uint32_t& l) {
    __nv_bfloat16 ha = __float2bfloat16(a);
    __nv_bfloat16 hb = __float2bfloat16(b);
    float ra = a - __bfloat162float(ha);
    float rb = b - __bfloat162float(hb);
    __nv_bfloat162 hv = __halves2bfloat162(ha, hb);
    __nv_bfloat162 lv = __floats2bfloat162_rn(ra, rb);
    h = *reinterpret_cast<uint32_t*>(&hv);
    l = *reinterpret_cast<uint32_t*>(&lv);
}

// ---------------------------------------------------------------------------
// 1) convert: split x and the 4 weight matrices into bf16 hi/lo
// ---------------------------------------------------------------------------
__global__ __launch_bounds__(256) void convert_split(const float* __restrict__ x,
                                                     const float* __restrict__ Wq,
                                                     const float* __restrict__ Wk,
                                                     const float* __restrict__ Wv,
                                                     const float* __restrict__ Wo)
{
    const int NX = Mm * Dd / 4;   // float4 count for x
    const int NW = Dd * Dd / 4;
    int i = blockIdx.x * 256 + threadIdx.x;
    if (i >= NX + 4 * NW) return;

    const float4* src;
    __nv_bfloat16 *dh, *dl;
    int off;
    if (i < NX) {
        src = (const float4*)x; dh = g_xh; dl = g_xl; off = i;
    } else {
        int j = i - NX;
        int w = j / NW;
        off = j % NW;
        const float* s = (w == 0) ? Wq : (w == 1) ? Wk : (w == 2) ? Wv : Wo;
        src = (const float4*)s;
        dh = g_Wh + (size_t)w * Dd * Dd;
        dl = g_Wl + (size_t)w * Dd * Dd;
    }
    float4 v = src[off];
    uint32_t h01, l01, h23, l23;
    split2(v.x, v.y, h01, l01);
    split2(v.z, v.w, h23, l23);
    uint2 hv = {h01, h23}, lv = {l01, l23};
    *(uint2*)&dh[(size_t)off * 4] = hv;
    *(uint2*)&dl[(size_t)off * 4] = lv;
}

// ---------------------------------------------------------------------------
// 2) tensor-core GEMM: y[m,n] = sum_k A[m,k]*W[n,k], 3-term bf16 split.
// Block 128m x 64n, 8 warps (warp tile 32x32), K chunks of 32.
// ---------------------------------------------------------------------------
constexpr int GST = 40;  // smem row stride in bf16 (conflict-free for ldmatrix)

template <int MODE>
__global__ __launch_bounds__(256, 2) void gemm_tc(const float* __restrict__ bias,
                                                  float* __restrict__ outd)
{
    __shared__ __nv_bfloat16 sAh[128 * GST], sAl[128 * GST];
    __shared__ __nv_bfloat16 sBh[64 * GST],  sBl[64 * GST];

    const int tid = threadIdx.x, lane = tid & 31, wid = tid >> 5;
    const int wm = wid & 3, wn = wid >> 2;        // warp grid 4m x 2n
    const int m0 = blockIdx.y * 128, n0 = blockIdx.x * 64;
    const int z = (MODE == 0) ? blockIdx.z : 3;

    const __nv_bfloat16* pAh = (MODE == 0) ? g_xh : g_ctxh;
    const __nv_bfloat16* pAl = (MODE == 0) ? g_xl : g_ctxl;
    const __nv_bfloat16* pBh = g_Wh + (size_t)z * Dd * Dd;
    const __nv_bfloat16* pBl = g_Wl + (size_t)z * Dd * Dd;

    const int lr = tid >> 3;          // 0..31
    const int lc = (tid & 7) * 4;     // bf16 col within 32-chunk

    uint2 rAh[4], rAl[4], rBh[2], rBl[2];

    auto loadg = [&](int k0) {
        const __nv_bfloat16* a_h = pAh + (size_t)(m0 + lr) * Dd + k0 + lc;
        const __nv_bfloat16* a_l = pAl + (size_t)(m0 + lr) * Dd + k0 + lc;
#pragma unroll
        for (int j = 0; j < 4; j++) {
            rAh[j] = *(const uint2*)(a_h + (size_t)j * 32 * Dd);
            rAl[j] = *(const uint2*)(a_l + (size_t)j * 32 * Dd);
        }
        const __nv_bfloat16* b_h = pBh + (size_t)(n0 + lr) * Dd + k0 + lc;
        const __nv_bfloat16* b_l = pBl + (size_t)(n0 + lr) * Dd + k0 + lc;
#pragma unroll
        for (int j = 0; j < 2; j++) {
            rBh[j] = *(const uint2*)(b_h + (size_t)j * 32 * Dd);
            rBl[j] = *(const uint2*)(b_l + (size_t)j * 32 * Dd);
        }
    };
    auto stores = [&]() {
#pragma unroll
        for (int j = 0; j < 4; j++) {
            *(uint2*)&sAh[(lr + 32 * j) * GST + lc] = rAh[j];
            *(uint2*)&sAl[(lr + 32 * j) * GST + lc] = rAl[j];
        }
#pragma unroll
        for (int j = 0; j < 2; j++) {
            *(uint2*)&sBh[(lr + 32 * j) * GST + lc] = rBh[j];
            *(uint2*)&sBl[(lr + 32 * j) * GST + lc] = rBl[j];
        }
    };

    float acc[2][4][4];
#pragma unroll
    for (int a = 0; a < 2; a++)
#pragma unroll
        for (int b = 0; b < 4; b++)
#pragma unroll
            for (int c = 0; c < 4; c++) acc[a][b][c] = 0.0f;

    const uint32_t aH = smaddr(sAh), aL = smaddr(sAl);
    const uint32_t bH = smaddr(sBh), bL = smaddr(sBl);

    loadg(0);
    for (int ch = 0; ch < Dd / 32; ch++) {
        __syncthreads();
        stores();
        __syncthreads();
        if (ch < Dd / 32 - 1) loadg((ch + 1) * 32);

#pragma unroll
        for (int ks = 0; ks < 2; ks++) {
            uint32_t ah[2][4], al[2][4], bh[2][4], bl[2][4];
            const int arow = wm * 32 + (lane & 15);
            const int acol = ks * 16 + (lane >> 4) * 8;
#pragma unroll
            for (int mt = 0; mt < 2; mt++) {
                uint32_t o = (uint32_t)(((arow + mt * 16) * GST + acol) * 2);
                ldsm4(ah[mt], aH + o);
                ldsm4(al[mt], aL + o);
            }
            const int g = lane >> 3;
            const int brow = wn * 32 + ((g >> 1) << 3) + (lane & 7);
            const int bcol = ks * 16 + ((g & 1) << 3);
#pragma unroll
            for (int p = 0; p < 2; p++) {
                uint32_t o = (uint32_t)(((brow + p * 16) * GST + bcol) * 2);
                ldsm4(bh[p], bH + o);
                ldsm4(bl[p], bL + o);
            }
#pragma unroll
            for (int mt = 0; mt < 2; mt++)
#pragma unroll
                for (int p = 0; p < 2; p++) {
                    mma16816(acc[mt][2 * p],     ah[mt], &bh[p][0]);
                    mma16816(acc[mt][2 * p],     ah[mt], &bl[p][0]);
                    mma16816(acc[mt][2 * p],     al[mt], &bh[p][0]);
                    mma16816(acc[mt][2 * p + 1], ah[mt], &bh[p][2]);
                    mma16816(acc[mt][2 * p + 1], ah[mt], &bl[p][2]);
                    mma16816(acc[mt][2 * p + 1], al[mt], &bh[p][2]);
                }
        }
    }

    // epilogue
    const int g4 = lane >> 2, q2 = (lane & 3) * 2;
    if (MODE == 0) {
        __nv_bfloat16* oh = (z == 0) ? g_Qh : (z == 1) ? g_Kh : g_Vh;
        __nv_bfloat16* ol = (z == 0) ? g_Ql : (z == 1) ? g_Kl : g_Vl;
#pragma unroll
        for (int mt = 0; mt < 2; mt++)
#pragma unroll
            for (int nt = 0; nt < 4; nt++) {
                int r0 = m0 + wm * 32 + mt * 16 + g4;
                int n  = n0 + wn * 32 + nt * 8 + q2;
                int b = r0 >> 11, s = r0 & 2047;
                int h = n >> 6,  d = n & 63;
                size_t i0 = (((size_t)(b * Hh + h)) * Ss + s) * HD + d;
                size_t i1 = i0 + (size_t)8 * HD;
                uint32_t hh, ll;
                split2(acc[mt][nt][0], acc[mt][nt][1], hh, ll);
                *(uint32_t*)&oh[i0] = hh; *(uint32_t*)&ol[i0] = ll;
                split2(acc[mt][nt][2], acc[mt][nt][3], hh, ll);
                *(uint32_t*)&oh[i1] = hh; *(uint32_t*)&ol[i1] = ll;
            }
    } else {
#pragma unroll
        for (int mt = 0; mt < 2; mt++)
#pragma unroll
            for (int nt = 0; nt < 4; nt++) {
                int r0 = m0 + wm * 32 + mt * 16 + g4;
                int n  = n0 + wn * 32 + nt * 8 + q2;
                float b0 = bias[n], b1 = bias[n + 1];
                float2 v0 = {acc[mt][nt][0] + b0, acc[mt][nt][1] + b1};
                float2 v1 = {acc[mt][nt][2] + b0, acc[mt][nt][3] + b1};
                *(float2*)&outd[(size_t)r0 * Dd + n] = v0;
                *(float2*)&outd[(size_t)(r0 + 8) * Dd + n] = v1;
            }
    }
}

// ---------------------------------------------------------------------------
// 3) tensor-core causal flash attention. Block = 128 thr (4 warps),
// q-tile 64 (16 rows per warp), k-tile 64, HD = 64.
// ---------------------------------------------------------------------------
constexpr int FST = 72;                             // bf16 row stride
constexpr int FLASH_SMEM = 6 * 64 * FST * 2;        // 55296 bytes

__global__ __launch_bounds__(128) void flash_tc()
{
    extern __shared__ __nv_bfloat16 fs[];
    __nv_bfloat16* sQh = fs;
    __nv_bfloat16* sQl = sQh + 64 * FST;
    __nv_bfloat16* sKh = sQl + 64 * FST;
    __nv_bfloat16* sKl = sKh + 64 * FST;
    __nv_bfloat16* sVh = sKl + 64 * FST;
    __nv_bfloat16* sVl = sVh + 64 * FST;

    const int tid = threadIdx.x, lane = tid & 31, wid = tid >> 5;
    const int qt = blockIdx.x, bhi = blockIdx.y;
    const size_t base = (size_t)bhi * Ss * HD;
    const float SCL = 0.125f * 1.4426950408889634f;  // 1/sqrt(HD) * log2(e)

    // load Q tile (64x64, hi+lo): 8 row-octets cover all 64 rows  [R3 bug: was 4]
#pragma unroll
    for (int j = 0; j < 8; j++) {
        int row = (tid >> 4) + 8 * j;
        int c4  = (tid & 15) * 4;
        size_t go = base + (size_t)(qt * 64 + row) * HD + c4;
        *(uint2*)&sQh[row * FST + c4] = *(const uint2*)&g_Qh[go];
        *(uint2*)&sQl[row * FST + c4] = *(const uint2*)&g_Ql[go];
    }

    float m0_ = -1e30f, m1_ = -1e30f, l0_ = 0.f, l1_ = 0.f;
    float o[8][4];
#pragma unroll
    for (int t = 0; t < 8; t++)
#pragma unroll
        for (int c = 0; c < 4; c++) o[t][c] = 0.f;

    const uint32_t aQh = smaddr(sQh), aQl = smaddr(sQl);
    const uint32_t aKh = smaddr(sKh), aKl = smaddr(sKl);
    const uint32_t aVh = smaddr(sVh), aVl = smaddr(sVl);

    for (int kt = 0; kt <= qt; kt++) {
        __syncthreads();
#pragma unroll
        for (int j = 0; j < 8; j++) {                 // [R3 bug: was 4]
            int row = (tid >> 4) + 8 * j;
            int c4  = (tid & 15) * 4;
            size_t go = base + (size_t)(kt * 64 + row) * HD + c4;
            *(uint2*)&sKh[row * FST + c4] = *(const uint2*)&g_Kh[go];
            *(uint2*)&sKl[row * FST + c4] = *(const uint2*)&g_Kl[go];
            *(uint2*)&sVh[row * FST + c4] = *(const uint2*)&g_Vh[go];
            *(uint2*)&sVl[row * FST + c4] = *(const uint2*)&g_Vl[go];
        }
        __syncthreads();

        // S = Q K^T (3-term)
        float s[8][4];
#pragma unroll
        for (int t = 0; t < 8; t++)
#pragma unroll
            for (int c = 0; c < 4; c++) s[t][c] = 0.f;

#pragma unroll
        for (int ks = 0; ks < 4; ks++) {
            uint32_t qh[4], ql[4];
            const int arow = wid * 16 + (lane & 15);
            const int acol = ks * 16 + (lane >> 4) * 8;
            ldsm4(qh, aQh + (uint32_t)((arow * FST + acol) * 2));
            ldsm4(ql, aQl + (uint32_t)((arow * FST + acol) * 2));
            const int g = lane >> 3;
            const int br = ((g >> 1) << 3) + (lane & 7);
            const int bc = ks * 16 + ((g & 1) << 3);
#pragma unroll
            for (int p = 0; p < 4; p++) {
                uint32_t kh[4], kl[4];
                uint32_t off = (uint32_t)(((br + p * 16) * FST + bc) * 2);
                ldsm4(kh, aKh + off);
                ldsm4(kl, aKl + off);
                mma16816(s[2 * p],     qh, &kh[0]);
                mma16816(s[2 * p],     qh, &kl[0]);
                mma16816(s[2 * p],     ql, &kh[0]);
                mma16816(s[2 * p + 1], qh, &kh[2]);
                mma16816(s[2 * p + 1], qh, &kl[2]);
                mma16816(s[2 * p + 1], ql, &kh[2]);
            }
        }

        // scale (base-2 domain) + causal mask + online softmax
        const int r0g = qt * 64 + wid * 16 + (lane >> 2);
        const int r1g = r0g + 8;
        const bool diag = (kt == qt);
        float mx0 = -1e30f, mx1 = -1e30f;
#pragma unroll
        for (int t = 0; t < 8; t++) {
            int cg = kt * 64 + t * 8 + (lane & 3) * 2;
            float v0 = s[t][0] * SCL, v1 = s[t][1] * SCL;
            float v2 = s[t][2] * SCL, v3 = s[t][3] * SCL;
            if (diag) {
                if (cg     > r0g) v0 = -1e30f;
                if (cg + 1 > r0g) v1 = -1e30f;
                if (cg     > r1g) v2 = -1e30f;
                if (cg + 1 > r1g) v3 = -1e30f;
            }
            s[t][0] = v0; s[t][1] = v1; s[t][2] = v2; s[t][3] = v3;
            mx0 = fmaxf(mx0, fmaxf(v0, v1));
            mx1 = fmaxf(mx1, fmaxf(v2, v3));
        }
        mx0 = fmaxf(mx0, __shfl_xor_sync(0xffffffffu, mx0, 1));
        mx0 = fmaxf(mx0, __shfl_xor_sync(0xffffffffu, mx0, 2));
        mx1 = fmaxf(mx1, __shfl_xor_sync(0xffffffffu, mx1, 1));
        mx1 = fmaxf(mx1, __shfl_xor_sync(0xffffffffu, mx1, 2));
        float nm0 = fmaxf(m0_, mx0), nm1 = fmaxf(m1_, mx1);
        float al0 = ex2f(m0_ - nm0), al1 = ex2f(m1_ - nm1);
        float sum0 = 0.f, sum1 = 0.f;
#pragma unroll
        for (int t = 0; t < 8; t++) {
            float p0 = ex2f(s[t][0] - nm0), p1 = ex2f(s[t][1] - nm0);
            float p2 = ex2f(s[t][2] - nm1), p3 = ex2f(s[t][3] - nm1);
            s[t][0] = p0; s[t][1] = p1; s[t][2] = p2; s[t][3] = p3;
            sum0 += p0 + p1; sum1 += p2 + p3;
        }
        sum0 += __shfl_xor_sync(0xffffffffu, sum0, 1);
        sum0 += __shfl_xor_sync(0xffffffffu, sum0, 2);
        sum1 += __shfl_xor_sync(0xffffffffu, sum1, 1);
        sum1 += __shfl_xor_sync(0xffffffffu, sum1, 2);
        l0_ = l0_ * al0 + sum0;
        l1_ = l1_ * al1 + sum1;
        m0_ = nm0; m1_ = nm1;
#pragma unroll
        for (int t = 0; t < 8; t++) {
            o[t][0] *= al0; o[t][1] *= al0;
            o[t][2] *= al1; o[t][3] *= al1;
        }

        // pack P into A-fragments (C-frag reuse), hi+lo
        uint32_t pah[4][4], pal[4][4];
#pragma unroll
        for (int t = 0; t < 4; t++) {
            split2(s[2 * t][0],     s[2 * t][1],     pah[t][0], pal[t][0]);
            split2(s[2 * t][2],     s[2 * t][3],     pah[t][1], pal[t][1]);
            split2(s[2 * t + 1][0], s[2 * t + 1][1], pah[t][2], pal[t][2]);
            split2(s[2 * t + 1][2], s[2 * t + 1][3], pah[t][3], pal[t][3]);
        }

        // O += P V (3-term), V fragments via ldmatrix.trans
        const int g = lane >> 3;
        const int vr = ((g & 1) << 3) + (lane & 7);
        const int vc = (lane >= 16) ? 8 : 0;
#pragma unroll
        for (int t = 0; t < 4; t++) {
#pragma unroll
            for (int dp = 0; dp < 4; dp++) {
                uint32_t vh[4], vl[4];
                uint32_t off = (uint32_t)(((t * 16 + vr) * FST + dp * 16 + vc) * 2);
                ldsm4t(vh, aVh + off);
                ldsm4t(vl, aVl + off);
                mma16816(o[2 * dp],     pah[t], &vh[0]);
                mma16816(o[2 * dp],     pah[t], &vl[0]);
                mma16816(o[2 * dp],     pal[t], &vh[0]);
                mma16816(o[2 * dp + 1], pah[t], &vh[2]);
                mma16816(o[2 * dp + 1], pah[t], &vl[2]);
                mma16816(o[2 * dp + 1], pal[t], &vh[2]);
            }
        }
    }

    // epilogue: normalize, split to bf16 hi/lo ctx [B*S, D]
    const int b = bhi >> 4, h = bhi & 15;
    const float i0 = 1.f / l0_, i1 = 1.f / l1_;
    const int r0 = qt * 64 + wid * 16 + (lane >> 2);
    const size_t row0 = (size_t)(b * Ss + r0) * Dd;
    const size_t row1 = row0 + (size_t)8 * Dd;
#pragma unroll
    for (int dt = 0; dt < 8; dt++) {
        int d = h * 64 + dt * 8 + (lane & 3) * 2;
        uint32_t hh, ll;
        split2(o[dt][0] * i0, o[dt][1] * i0, hh, ll);
        *(uint32_t*)&g_ctxh[row0 + d] = hh;
        *(uint32_t*)&g_ctxl[row0 + d] = ll;
        split2(o[dt][2] * i1, o[dt][3] * i1, hh, ll);
        *(uint32_t*)&g_ctxh[row1 + d] = hh;
        *(uint32_t*)&g_ctxl[row1 + d] = ll;
    }
}

// ---------------------------------------------------------------------------
extern "C" void kernel_launch(void* const* d_in, const int* in_sizes, int n_in,
                              void* d_out, int out_size)
{
    const float* x  = (const float*)d_in[0];
    const float* Wq = (const float*)d_in[1];
    const float* Wk = (const float*)d_in[2];
    const float* Wv = (const float*)d_in[3];
    const float* Wo = (const float*)d_in[4];
    const float* bo = (const float*)d_in[5];
    float* out = (float*)d_out;

    cudaFuncSetAttribute(flash_tc, cudaFuncAttributeMaxDynamicSharedMemorySize,
                         FLASH_SMEM);

    // 1) split inputs to bf16 hi/lo
    convert_split<<<(Mm * Dd / 4 + 4 * Dd * Dd / 4 + 255) / 256, 256>>>(
        x, Wq, Wk, Wv, Wo);

    // 2) QKV projections
    gemm_tc<0><<<dim3(Dd / 64, Mm / 128, 3), 256>>>(nullptr, nullptr);

    // 3) causal flash attention
    flash_tc<<<dim3(Ss / 64, Bb * Hh), 128, FLASH_SMEM>>>();

    // 4) output projection + bias
    gemm_tc<1><<<dim3(Dd / 64, Mm / 128, 1), 256>>>(bo, out);
}

// round 5
// speedup vs baseline: 2.7102x; 1.0573x over previous
#include <cuda_runtime.h>
#include <cuda_bf16.h>
#include <cstdint>

constexpr int Bb = 2, Ss = 2048, Dd = 1024, Hh = 16, HD = 64;
constexpr int Mm = Bb * Ss;  // 4096

// bf16 hi/lo split scratch (allocation-free rule: __device__ globals)
__device__ __align__(256) __nv_bfloat16 g_xh[Mm * Dd],  g_xl[Mm * Dd];
__device__ __align__(256) __nv_bfloat16 g_Wh[4 * Dd * Dd], g_Wl[4 * Dd * Dd];
__device__ __align__(256) __nv_bfloat16 g_Qh[Mm * Dd],  g_Ql[Mm * Dd];   // [B,H,S,HD]
__device__ __align__(256) __nv_bfloat16 g_Kh[Mm * Dd],  g_Kl[Mm * Dd];
__device__ __align__(256) __nv_bfloat16 g_Vh[Mm * Dd],  g_Vl[Mm * Dd];
__device__ __align__(256) __nv_bfloat16 g_ctxh[Mm * Dd], g_ctxl[Mm * Dd]; // [B*S, D]

// ---------------------------------------------------------------------------
// helpers
// ---------------------------------------------------------------------------
__device__ __forceinline__ uint32_t smaddr(const void* p) {
    uint32_t a;
    asm("{ .reg .u64 t; cvta.to.shared.u64 t, %1; cvt.u32.u64 %0, t; }"
        : "=r"(a) : "l"(p));
    return a;
}
__device__ __forceinline__ void ldsm4(uint32_t* r, uint32_t a) {
    asm volatile("ldmatrix.sync.aligned.m8n8.x4.shared.b16 {%0,%1,%2,%3}, [%4];"
                 : "=r"(r[0]), "=r"(r[1]), "=r"(r[2]), "=r"(r[3]) : "r"(a));
}
__device__ __forceinline__ void ldsm4t(uint32_t* r, uint32_t a) {
    asm volatile("ldmatrix.sync.aligned.m8n8.x4.trans.shared.b16 {%0,%1,%2,%3}, [%4];"
                 : "=r"(r[0]), "=r"(r[1]), "=r"(r[2]), "=r"(r[3]) : "r"(a));
}
__device__ __forceinline__ void mma16816(float* c, const uint32_t* a, const uint32_t* b) {
    asm volatile(
        "mma.sync.aligned.m16n8k16.row.col.f32.bf16.bf16.f32 "
        "{%0,%1,%2,%3}, {%4,%5,%6,%7}, {%8,%9}, {%0,%1,%2,%3};"
        : "+f"(c[0]), "+f"(c[1]), "+f"(c[2]), "+f"(c[3])
        : "r"(a[0]), "r"(a[1]), "r"(a[2]), "r"(a[3]), "r"(b[0]), "r"(b[1]));
}
__device__ __forceinline__ float ex2f(float x) {
    float y;
    asm("ex2.approx.ftz.f32 %0, %1;" : "=f"(y) : "f"(x));
    return y;
}
__device__ __forceinline__ void cp16(uint32_t dst, const void* src) {
    asm volatile("cp.async.cg.shared.global [%0], [%1], 16;" :: "r"(dst), "l"(src));
}
#define CP_COMMIT() asm volatile("cp.async.commit_group;" ::: "memory")
#define CP_WAIT1()  asm volatile("cp.async.wait_group 1;" ::: "memory")
#define CP_WAIT0()  asm volatile("cp.async.wait_group 0;" ::: "memory")

// fp32 -> (bf16 hi, bf16 lo) for two values, packed as bf16x2 words
__device__ __forceinline__ void split2(float a, float b, uint32_t& h, uint32_t& l) {
    __nv_bfloat16 ha = __float2bfloat16(a);
    __nv_bfloat16 hb = __float2bfloat16(b);
    float ra = a - __bfloat162float(ha);
    float rb = b - __bfloat162float(hb);
    __nv_bfloat162 hv = __halves2bfloat162(ha, hb);
    __nv_bfloat162 lv = __floats2bfloat162_rn(ra, rb);
    h = *reinterpret_cast<uint32_t*>(&hv);
    l = *reinterpret_cast<uint32_t*>(&lv);
}

// ---------------------------------------------------------------------------
// 1) convert: split x and the 4 weight matrices into bf16 hi/lo
// ---------------------------------------------------------------------------
__global__ __launch_bounds__(256) void convert_split(const float* __restrict__ x,
                                                     const float* __restrict__ Wq,
                                                     const float* __restrict__ Wk,
                                                     const float* __restrict__ Wv,
                                                     const float* __restrict__ Wo)
{
    const int NX = Mm * Dd / 4;
    const int NW = Dd * Dd / 4;
    int i = blockIdx.x * 256 + threadIdx.x;
    if (i >= NX + 4 * NW) return;

    const float4* src;
    __nv_bfloat16 *dh, *dl;
    int off;
    if (i < NX) {
        src = (const float4*)x; dh = g_xh; dl = g_xl; off = i;
    } else {
        int j = i - NX;
        int w = j / NW;
        off = j % NW;
        const float* s = (w == 0) ? Wq : (w == 1) ? Wk : (w == 2) ? Wv : Wo;
        src = (const float4*)s;
        dh = g_Wh + (size_t)w * Dd * Dd;
        dl = g_Wl + (size_t)w * Dd * Dd;
    }
    float4 v = src[off];
    uint32_t h01, l01, h23, l23;
    split2(v.x, v.y, h01, l01);
    split2(v.z, v.w, h23, l23);
    uint2 hv = {h01, h23}, lv = {l01, l23};
    *(uint2*)&dh[(size_t)off * 4] = hv;
    *(uint2*)&dl[(size_t)off * 4] = lv;
}

// ---------------------------------------------------------------------------
// 2) tensor-core GEMM v2: 128x128 block, 8 warps (warp tile 64x32),
//    3-stage cp.async pipeline, K chunks of 32, 3-term bf16 split.
// ---------------------------------------------------------------------------
constexpr int GST    = 40;                 // smem bf16 row stride (conflict-free)
constexpr int TILEB  = 128 * GST * 2;      // 10240 B per (array, stage)
constexpr int STAGEB = 4 * TILEB;          // Ah, Al, Bh, Bl
constexpr int GEMM_SMEM = 3 * STAGEB;      // 122880 B

template <int MODE>
__global__ __launch_bounds__(256, 1) void gemm_tc(const float* __restrict__ bias,
                                                  float* __restrict__ outd)
{
    extern __shared__ char smc[];
    const uint32_t sb = smaddr(smc);
    const int tid = threadIdx.x, lane = tid & 31, wid = tid >> 5;
    const int wm = wid & 1, wn = wid >> 1;           // warp grid 2m x 4n
    const int m0 = blockIdx.y * 128, n0 = blockIdx.x * 128;
    const int z = (MODE == 0) ? blockIdx.z : 3;

    const __nv_bfloat16* pAh = (MODE == 0) ? g_xh : g_ctxh;
    const __nv_bfloat16* pAl = (MODE == 0) ? g_xl : g_ctxl;
    const __nv_bfloat16* pBh = g_Wh + (size_t)z * Dd * Dd;
    const __nv_bfloat16* pBl = g_Wl + (size_t)z * Dd * Dd;

    const __nv_bfloat16* srcs[4] = {pAh, pAl, pBh, pBl};
    const int rb[4] = {m0, m0, n0, n0};

    // stage issue: 8 x 16B cp.async per thread (2 per array)
    auto issue = [&](int ch, int st) {
        const int k0 = ch * 32;
        const uint32_t stb = sb + st * STAGEB;
#pragma unroll
        for (int j = 0; j < 8; j++) {
            int arr = j >> 1;
            int c   = (j & 1) * 256 + tid;       // 0..511
            int row = c >> 2;                    // 0..127
            int kq  = (c & 3) * 8;               // bf16 col
            uint32_t dst = stb + arr * TILEB + (uint32_t)(row * GST + kq) * 2;
            cp16(dst, srcs[arr] + (size_t)(rb[arr] + row) * Dd + k0 + kq);
        }
        CP_COMMIT();
    };

    float acc[4][4][4];
#pragma unroll
    for (int a = 0; a < 4; a++)
#pragma unroll
        for (int b = 0; b < 4; b++)
#pragma unroll
            for (int c = 0; c < 4; c++) acc[a][b][c] = 0.0f;

    issue(0, 0);
    issue(1, 1);

    constexpr int NCH = Dd / 32;   // 32
    for (int ch = 0; ch < NCH; ch++) {
        if (ch < NCH - 1) CP_WAIT1(); else CP_WAIT0();
        __syncthreads();
        if (ch + 2 < NCH) issue(ch + 2, (ch + 2) % 3);

        const uint32_t stb = sb + (ch % 3) * STAGEB;
        const uint32_t aAh = stb, aAl = stb + TILEB;
        const uint32_t aBh = stb + 2 * TILEB, aBl = stb + 3 * TILEB;

#pragma unroll
        for (int ks = 0; ks < 2; ks++) {
            uint32_t ah[4][4], al[4][4], bh[2][4], bl[2][4];
            const int arow = wm * 64 + (lane & 15);
            const int acol = ks * 16 + (lane >> 4) * 8;
#pragma unroll
            for (int mt = 0; mt < 4; mt++) {
                uint32_t o = (uint32_t)(((arow + mt * 16) * GST + acol) * 2);
                ldsm4(ah[mt], aAh + o);
                ldsm4(al[mt], aAl + o);
            }
            const int g = lane >> 3;
            const int brow = wn * 32 + ((g >> 1) << 3) + (lane & 7);
            const int bcol = ks * 16 + ((g & 1) << 3);
#pragma unroll
            for (int p = 0; p < 2; p++) {
                uint32_t o = (uint32_t)(((brow + p * 16) * GST + bcol) * 2);
                ldsm4(bh[p], aBh + o);
                ldsm4(bl[p], aBl + o);
            }
#pragma unroll
            for (int mt = 0; mt < 4; mt++)
#pragma unroll
                for (int p = 0; p < 2; p++) {
                    mma16816(acc[mt][2 * p],     ah[mt], &bh[p][0]);
                    mma16816(acc[mt][2 * p],     ah[mt], &bl[p][0]);
                    mma16816(acc[mt][2 * p],     al[mt], &bh[p][0]);
                    mma16816(acc[mt][2 * p + 1], ah[mt], &bh[p][2]);
                    mma16816(acc[mt][2 * p + 1], ah[mt], &bl[p][2]);
                    mma16816(acc[mt][2 * p + 1], al[mt], &bh[p][2]);
                }
        }
        __syncthreads();
    }

    // epilogue
    const int g4 = lane >> 2, q2 = (lane & 3) * 2;
    if (MODE == 0) {
        __nv_bfloat16* oh = (z == 0) ? g_Qh : (z == 1) ? g_Kh : g_Vh;
        __nv_bfloat16* ol = (z == 0) ? g_Ql : (z == 1) ? g_Kl : g_Vl;
#pragma unroll
        for (int mt = 0; mt < 4; mt++)
#pragma unroll
            for (int nt = 0; nt < 4; nt++) {
                int r0 = m0 + wm * 64 + mt * 16 + g4;
                int n  = n0 + wn * 32 + nt * 8 + q2;
                int b = r0 >> 11, s = r0 & 2047;
                int h = n >> 6,  d = n & 63;
                size_t i0 = (((size_t)(b * Hh + h)) * Ss + s) * HD + d;
                size_t i1 = i0 + (size_t)8 * HD;
                uint32_t hh, ll;
                split2(acc[mt][nt][0], acc[mt][nt][1], hh, ll);
                *(uint32_t*)&oh[i0] = hh; *(uint32_t*)&ol[i0] = ll;
                split2(acc[mt][nt][2], acc[mt][nt][3], hh, ll);
                *(uint32_t*)&oh[i1] = hh; *(uint32_t*)&ol[i1] = ll;
            }
    } else {
#pragma unroll
        for (int mt = 0; mt < 4; mt++)
#pragma unroll
            for (int nt = 0; nt < 4; nt++) {
                int r0 = m0 + wm * 64 + mt * 16 + g4;
                int n  = n0 + wn * 32 + nt * 8 + q2;
                float b0 = bias[n], b1 = bias[n + 1];
                float2 v0 = {acc[mt][nt][0] + b0, acc[mt][nt][1] + b1};
                float2 v1 = {acc[mt][nt][2] + b0, acc[mt][nt][3] + b1};
                *(float2*)&outd[(size_t)r0 * Dd + n] = v0;
                *(float2*)&outd[(size_t)(r0 + 8) * Dd + n] = v1;
            }
    }
}

// ---------------------------------------------------------------------------
// 3) tensor-core causal flash attention, cp.async double-buffered K/V.
// Block = 128 thr (4 warps), q-tile 64, k-tile 64, HD = 64.
// ---------------------------------------------------------------------------
constexpr int FST  = 72;              // bf16 row stride
constexpr int FARR = 64 * FST * 2;    // 9216 B per array
// layout: [Qh, Ql, st0:{Kh,Kl,Vh,Vl}, st1:{Kh,Kl,Vh,Vl}]
constexpr int FLASH_SMEM = 10 * FARR; // 92160 B

__global__ __launch_bounds__(128) void flash_tc()
{
    extern __shared__ char fsc[];
    __nv_bfloat16* fs = (__nv_bfloat16*)fsc;
    const uint32_t sb = smaddr(fsc);

    const int tid = threadIdx.x, lane = tid & 31, wid = tid >> 5;
    const int qt = blockIdx.x, bhi = blockIdx.y;
    const size_t base = (size_t)bhi * Ss * HD;
    const float SCL = 0.125f * 1.4426950408889634f;  // 1/sqrt(HD) * log2(e)

    const __nv_bfloat16* ksrc[4] = {g_Kh + base, g_Kl + base, g_Vh + base, g_Vl + base};

    // issue one K/V stage: 16 x 16B cp.async per thread (4 per array)
    auto issue_kv = [&](int kt, int st) {
        const uint32_t stb = sb + (2 + st * 4) * FARR;
#pragma unroll
        for (int j = 0; j < 16; j++) {
            int arr = j >> 2;
            int c   = (j & 3) * 128 + tid;     // 0..511
            int row = c >> 3;                  // 0..63
            int c8  = (c & 7) * 8;             // bf16 col
            uint32_t dst = stb + arr * FARR + (uint32_t)(row * FST + c8) * 2;
            cp16(dst, ksrc[arr] + (size_t)(kt * 64 + row) * HD + c8);
        }
        CP_COMMIT();
    };

    issue_kv(0, 0);

    // load Q tile (plain loads; overlap with cp.async in flight)
    __nv_bfloat16* sQh = fs;
    __nv_bfloat16* sQl = fs + 64 * FST;
#pragma unroll
    for (int j = 0; j < 8; j++) {
        int row = (tid >> 4) + 8 * j;
        int c4  = (tid & 15) * 4;
        size_t go = base + (size_t)(qt * 64 + row) * HD + c4;
        *(uint2*)&sQh[row * FST + c4] = *(const uint2*)&g_Qh[go];
        *(uint2*)&sQl[row * FST + c4] = *(const uint2*)&g_Ql[go];
    }

    float m0_ = -1e30f, m1_ = -1e30f, l0_ = 0.f, l1_ = 0.f;
    float o[8][4];
#pragma unroll
    for (int t = 0; t < 8; t++)
#pragma unroll
        for (int c = 0; c < 4; c++) o[t][c] = 0.f;

    const uint32_t aQh = sb, aQl = sb + FARR;

    for (int kt = 0; kt <= qt; kt++) {
        if (kt < qt) { issue_kv(kt + 1, (kt + 1) & 1); CP_WAIT1(); }
        else         { CP_WAIT0(); }
        __syncthreads();

        const uint32_t stb = sb + (uint32_t)(2 + (kt & 1) * 4) * FARR;
        const uint32_t aKh = stb, aKl = stb + FARR;
        const uint32_t aVh = stb + 2 * FARR, aVl = stb + 3 * FARR;

        // S = Q K^T (3-term)
        float s[8][4];
#pragma unroll
        for (int t = 0; t < 8; t++)
#pragma unroll
            for (int c = 0; c < 4; c++) s[t][c] = 0.f;

#pragma unroll
        for (int ks = 0; ks < 4; ks++) {
            uint32_t qh[4], ql[4];
            const int arow = wid * 16 + (lane & 15);
            const int acol = ks * 16 + (lane >> 4) * 8;
            ldsm4(qh, aQh + (uint32_t)((arow * FST + acol) * 2));
            ldsm4(ql, aQl + (uint32_t)((arow * FST + acol) * 2));
            const int g = lane >> 3;
            const int br = ((g >> 1) << 3) + (lane & 7);
            const int bc = ks * 16 + ((g & 1) << 3);
#pragma unroll
            for (int p = 0; p < 4; p++) {
                uint32_t kh[4], kl[4];
                uint32_t off = (uint32_t)(((br + p * 16) * FST + bc) * 2);
                ldsm4(kh, aKh + off);
                ldsm4(kl, aKl + off);
                mma16816(s[2 * p],     qh, &kh[0]);
                mma16816(s[2 * p],     qh, &kl[0]);
                mma16816(s[2 * p],     ql, &kh[0]);
                mma16816(s[2 * p + 1], qh, &kh[2]);
                mma16816(s[2 * p + 1], qh, &kl[2]);
                mma16816(s[2 * p + 1], ql, &kh[2]);
            }
        }

        // scale (base-2) + causal mask + online softmax
        const int r0g = qt * 64 + wid * 16 + (lane >> 2);
        const int r1g = r0g + 8;
        const bool diag = (kt == qt);
        float mx0 = -1e30f, mx1 = -1e30f;
#pragma unroll
        for (int t = 0; t < 8; t++) {
            int cg = kt * 64 + t * 8 + (lane & 3) * 2;
            float v0 = s[t][0] * SCL, v1 = s[t][1] * SCL;
            float v2 = s[t][2] * SCL, v3 = s[t][3] * SCL;
            if (diag) {
                if (cg     > r0g) v0 = -1e30f;
                if (cg + 1 > r0g) v1 = -1e30f;
                if (cg     > r1g) v2 = -1e30f;
                if (cg + 1 > r1g) v3 = -1e30f;
            }
            s[t][0] = v0; s[t][1] = v1; s[t][2] = v2; s[t][3] = v3;
            mx0 = fmaxf(mx0, fmaxf(v0, v1));
            mx1 = fmaxf(mx1, fmaxf(v2, v3));
        }
        mx0 = fmaxf(mx0, __shfl_xor_sync(0xffffffffu, mx0, 1));
        mx0 = fmaxf(mx0, __shfl_xor_sync(0xffffffffu, mx0, 2));
        mx1 = fmaxf(mx1, __shfl_xor_sync(0xffffffffu, mx1, 1));
        mx1 = fmaxf(mx1, __shfl_xor_sync(0xffffffffu, mx1, 2));
        float nm0 = fmaxf(m0_, mx0), nm1 = fmaxf(m1_, mx1);
        float al0 = ex2f(m0_ - nm0), al1 = ex2f(m1_ - nm1);
        float sum0 = 0.f, sum1 = 0.f;
#pragma unroll
        for (int t = 0; t < 8; t++) {
            float p0 = ex2f(s[t][0] - nm0), p1 = ex2f(s[t][1] - nm0);
            float p2 = ex2f(s[t][2] - nm1), p3 = ex2f(s[t][3] - nm1);
            s[t][0] = p0; s[t][1] = p1; s[t][2] = p2; s[t][3] = p3;
            sum0 += p0 + p1; sum1 += p2 + p3;
        }
        sum0 += __shfl_xor_sync(0xffffffffu, sum0, 1);
        sum0 += __shfl_xor_sync(0xffffffffu, sum0, 2);
        sum1 += __shfl_xor_sync(0xffffffffu, sum1, 1);
        sum1 += __shfl_xor_sync(0xffffffffu, sum1, 2);
        l0_ = l0_ * al0 + sum0;
        l1_ = l1_ * al1 + sum1;
        m0_ = nm0; m1_ = nm1;
#pragma unroll
        for (int t = 0; t < 8; t++) {
            o[t][0] *= al0; o[t][1] *= al0;
            o[t][2] *= al1; o[t][3] *= al1;
        }

        // pack P into A-fragments (C-frag reuse), hi+lo
        uint32_t pah[4][4], pal[4][4];
#pragma unroll
        for (int t = 0; t < 4; t++) {
            split2(s[2 * t][0],     s[2 * t][1],     pah[t][0], pal[t][0]);
            split2(s[2 * t][2],     s[2 * t][3],     pah[t][1], pal[t][1]);
            split2(s[2 * t + 1][0], s[2 * t + 1][1], pah[t][2], pal[t][2]);
            split2(s[2 * t + 1][2], s[2 * t + 1][3], pah[t][3], pal[t][3]);
        }

        // O += P V (3-term), V fragments via ldmatrix.trans
        const int g = lane >> 3;
        const int vr = ((g & 1) << 3) + (lane & 7);
        const int vc = (lane >= 16) ? 8 : 0;
#pragma unroll
        for (int t = 0; t < 4; t++) {
#pragma unroll
            for (int dp = 0; dp < 4; dp++) {
                uint32_t vh[4], vl[4];
                uint32_t off = (uint32_t)(((t * 16 + vr) * FST + dp * 16 + vc) * 2);
                ldsm4t(vh, aVh + off);
                ldsm4t(vl, aVl + off);
                mma16816(o[2 * dp],     pah[t], &vh[0]);
                mma16816(o[2 * dp],     pah[t], &vl[0]);
                mma16816(o[2 * dp],     pal[t], &vh[0]);
                mma16816(o[2 * dp + 1], pah[t], &vh[2]);
                mma16816(o[2 * dp + 1], pah[t], &vl[2]);
                mma16816(o[2 * dp + 1], pal[t], &vh[2]);
            }
        }
        __syncthreads();   // stage (kt&1) fully consumed before iter kt+1 overwrites (kt+2)&1
    }

    // epilogue: normalize, split to bf16 hi/lo ctx [B*S, D]
    const int b = bhi >> 4, h = bhi & 15;
    const float i0 = 1.f / l0_, i1 = 1.f / l1_;
    const int r0 = qt * 64 + wid * 16 + (lane >> 2);
    const size_t row0 = (size_t)(b * Ss + r0) * Dd;
    const size_t row1 = row0 + (size_t)8 * Dd;
#pragma unroll
    for (int dt = 0; dt < 8; dt++) {
        int d = h * 64 + dt * 8 + (lane & 3) * 2;
        uint32_t hh, ll;
        split2(o[dt][0] * i0, o[dt][1] * i0, hh, ll);
        *(uint32_t*)&g_ctxh[row0 + d] = hh;
        *(uint32_t*)&g_ctxl[row0 + d] = ll;
        split2(o[dt][2] * i1, o[dt][3] * i1, hh, ll);
        *(uint32_t*)&g_ctxh[row1 + d] = hh;
        *(uint32_t*)&g_ctxl[row1 + d] = ll;
    }
}

// ---------------------------------------------------------------------------
extern "C" void kernel_launch(void* const* d_in, const int* in_sizes, int n_in,
                              void* d_out, int out_size)
{
    const float* x  = (const float*)d_in[0];
    const float* Wq = (const float*)d_in[1];
    const float* Wk = (const float*)d_in[2];
    const float* Wv = (const float*)d_in[3];
    const float* Wo = (const float*)d_in[4];
    const float* bo = (const float*)d_in[5];
    float* out = (float*)d_out;

    cudaFuncSetAttribute(gemm_tc<0>, cudaFuncAttributeMaxDynamicSharedMemorySize,
                         GEMM_SMEM);
    cudaFuncSetAttribute(gemm_tc<1>, cudaFuncAttributeMaxDynamicSharedMemorySize,
                         GEMM_SMEM);
    cudaFuncSetAttribute(flash_tc, cudaFuncAttributeMaxDynamicSharedMemorySize,
                         FLASH_SMEM);

    // 1) split inputs to bf16 hi/lo
    convert_split<<<(Mm * Dd / 4 + 4 * Dd * Dd / 4 + 255) / 256, 256>>>(
        x, Wq, Wk, Wv, Wo);

    // 2) QKV projections
    gemm_tc<0><<<dim3(Dd / 128, Mm / 128, 3), 256, GEMM_SMEM>>>(nullptr, nullptr);

    // 3) causal flash attention
    flash_tc<<<dim3(Ss / 64, Bb * Hh), 128, FLASH_SMEM>>>();

    // 4) output projection + bias
    gemm_tc<1><<<dim3(Dd / 128, Mm / 128, 1), 256, GEMM_SMEM>>>(bo, out);
}

// round 6
// speedup vs baseline: 3.0086x; 1.1101x over previous
#include <cuda_runtime.h>
#include <cuda_bf16.h>
#include <cstdint>

constexpr int Bb = 2, Ss = 2048, Dd = 1024, Hh = 16, HD = 64;
constexpr int Mm = Bb * Ss;  // 4096

// bf16 hi/lo split scratch (allocation-free rule: __device__ globals)
__device__ __align__(256) __nv_bfloat16 g_xh[Mm * Dd],  g_xl[Mm * Dd];
__device__ __align__(256) __nv_bfloat16 g_Wh[4 * Dd * Dd], g_Wl[4 * Dd * Dd];
__device__ __align__(256) __nv_bfloat16 g_Qh[Mm * Dd],  g_Ql[Mm * Dd];   // [B,H,S,HD]
__device__ __align__(256) __nv_bfloat16 g_Kh[Mm * Dd],  g_Kl[Mm * Dd];
__device__ __align__(256) __nv_bfloat16 g_Vh[Mm * Dd],  g_Vl[Mm * Dd];
__device__ __align__(256) __nv_bfloat16 g_ctxh[Mm * Dd], g_ctxl[Mm * Dd]; // [B*S, D]

// ---------------------------------------------------------------------------
// helpers
// ---------------------------------------------------------------------------
__device__ __forceinline__ uint32_t smaddr(const void* p) {
    uint32_t a;
    asm("{ .reg .u64 t; cvta.to.shared.u64 t, %1; cvt.u32.u64 %0, t; }"
        : "=r"(a) : "l"(p));
    return a;
}
__device__ __forceinline__ void ldsm4(uint32_t* r, uint32_t a) {
    asm volatile("ldmatrix.sync.aligned.m8n8.x4.shared.b16 {%0,%1,%2,%3}, [%4];"
                 : "=r"(r[0]), "=r"(r[1]), "=r"(r[2]), "=r"(r[3]) : "r"(a));
}
__device__ __forceinline__ void ldsm4t(uint32_t* r, uint32_t a) {
    asm volatile("ldmatrix.sync.aligned.m8n8.x4.trans.shared.b16 {%0,%1,%2,%3}, [%4];"
                 : "=r"(r[0]), "=r"(r[1]), "=r"(r[2]), "=r"(r[3]) : "r"(a));
}
__device__ __forceinline__ void mma16816(float* c, const uint32_t* a, const uint32_t* b) {
    asm volatile(
        "mma.sync.aligned.m16n8k16.row.col.f32.bf16.bf16.f32 "
        "{%0,%1,%2,%3}, {%4,%5,%6,%7}, {%8,%9}, {%0,%1,%2,%3};"
        : "+f"(c[0]), "+f"(c[1]), "+f"(c[2]), "+f"(c[3])
        : "r"(a[0]), "r"(a[1]), "r"(a[2]), "r"(a[3]), "r"(b[0]), "r"(b[1]));
}
__device__ __forceinline__ float ex2f(float x) {
    float y;
    asm("ex2.approx.ftz.f32 %0, %1;" : "=f"(y) : "f"(x));
    return y;
}
__device__ __forceinline__ void cp16(uint32_t dst, const void* src) {
    asm volatile("cp.async.cg.shared.global [%0], [%1], 16;" :: "r"(dst), "l"(src));
}
#define CP_COMMIT() asm volatile("cp.async.commit_group;" ::: "memory")
#define CP_WAIT1()  asm volatile("cp.async.wait_group 1;" ::: "memory")
#define CP_WAIT0()  asm volatile("cp.async.wait_group 0;" ::: "memory")

// fp32 -> (bf16 hi, bf16 lo) for two values, packed as bf16x2 words
__device__ __forceinline__ void split2(float a, float b, uint32_t& h, uint32_t& l) {
    __nv_bfloat16 ha = __float2bfloat16(a);
    __nv_bfloat16 hb = __float2bfloat16(b);
    float ra = a - __bfloat162float(ha);
    float rb = b - __bfloat162float(hb);
    __nv_bfloat162 hv = __halves2bfloat162(ha, hb);
    __nv_bfloat162 lv = __floats2bfloat162_rn(ra, rb);
    h = *reinterpret_cast<uint32_t*>(&hv);
    l = *reinterpret_cast<uint32_t*>(&lv);
}

// ---------------------------------------------------------------------------
// 1) convert: split x and the 4 weight matrices into bf16 hi/lo
// ---------------------------------------------------------------------------
__global__ __launch_bounds__(256) void convert_split(const float* __restrict__ x,
                                                     const float* __restrict__ Wq,
                                                     const float* __restrict__ Wk,
                                                     const float* __restrict__ Wv,
                                                     const float* __restrict__ Wo)
{
    const int NX = Mm * Dd / 4;
    const int NW = Dd * Dd / 4;
    int i = blockIdx.x * 256 + threadIdx.x;
    if (i >= NX + 4 * NW) return;

    const float4* src;
    __nv_bfloat16 *dh, *dl;
    int off;
    if (i < NX) {
        src = (const float4*)x; dh = g_xh; dl = g_xl; off = i;
    } else {
        int j = i - NX;
        int w = j / NW;
        off = j % NW;
        const float* s = (w == 0) ? Wq : (w == 1) ? Wk : (w == 2) ? Wv : Wo;
        src = (const float4*)s;
        dh = g_Wh + (size_t)w * Dd * Dd;
        dl = g_Wl + (size_t)w * Dd * Dd;
    }
    float4 v = src[off];
    uint32_t h01, l01, h23, l23;
    split2(v.x, v.y, h01, l01);
    split2(v.z, v.w, h23, l23);
    uint2 hv = {h01, h23}, lv = {l01, l23};
    *(uint2*)&dh[(size_t)off * 4] = hv;
    *(uint2*)&dl[(size_t)off * 4] = lv;
}

// ---------------------------------------------------------------------------
// 2) tensor-core GEMM v3: 128x128 block, 8 warps (warp tile 64x32),
//    2-stage cp.async pipeline, 2 CTAs/SM (reg cap 128), 3-term bf16 split.
// ---------------------------------------------------------------------------
constexpr int GST    = 40;                 // smem bf16 row stride (conflict-free)
constexpr int TILEB  = 128 * GST * 2;      // 10240 B per (array, stage)
constexpr int STAGEB = 4 * TILEB;          // Ah, Al, Bh, Bl
constexpr int GEMM_SMEM = 2 * STAGEB;      // 81920 B -> 2 CTAs/SM

template <int MODE>
__global__ __launch_bounds__(256, 2) void gemm_tc(const float* __restrict__ bias,
                                                  float* __restrict__ outd)
{
    extern __shared__ char smc[];
    const uint32_t sb = smaddr(smc);
    const int tid = threadIdx.x, lane = tid & 31, wid = tid >> 5;
    const int wm = wid & 1, wn = wid >> 1;           // warp grid 2m x 4n
    const int m0 = blockIdx.y * 128, n0 = blockIdx.x * 128;
    const int z = (MODE == 0) ? blockIdx.z : 3;

    const __nv_bfloat16* pAh = (MODE == 0) ? g_xh : g_ctxh;
    const __nv_bfloat16* pAl = (MODE == 0) ? g_xl : g_ctxl;
    const __nv_bfloat16* pBh = g_Wh + (size_t)z * Dd * Dd;
    const __nv_bfloat16* pBl = g_Wl + (size_t)z * Dd * Dd;

    const __nv_bfloat16* srcs[4] = {pAh, pAl, pBh, pBl};
    const int rb[4] = {m0, m0, n0, n0};

    // stage issue: 8 x 16B cp.async per thread (2 per array)
    auto issue = [&](int ch, int st) {
        const int k0 = ch * 32;
        const uint32_t stb = sb + st * STAGEB;
#pragma unroll
        for (int j = 0; j < 8; j++) {
            int arr = j >> 1;
            int c   = (j & 1) * 256 + tid;       // 0..511
            int row = c >> 2;                    // 0..127
            int kq  = (c & 3) * 8;               // bf16 col
            uint32_t dst = stb + arr * TILEB + (uint32_t)(row * GST + kq) * 2;
            cp16(dst, srcs[arr] + (size_t)(rb[arr] + row) * Dd + k0 + kq);
        }
        CP_COMMIT();
    };

    float acc[4][4][4];
#pragma unroll
    for (int a = 0; a < 4; a++)
#pragma unroll
        for (int b = 0; b < 4; b++)
#pragma unroll
            for (int c = 0; c < 4; c++) acc[a][b][c] = 0.0f;

    issue(0, 0);
    issue(1, 1);

    constexpr int NCH = Dd / 32;   // 32
    for (int ch = 0; ch < NCH; ch++) {
        if (ch < NCH - 1) CP_WAIT1(); else CP_WAIT0();
        __syncthreads();            // stage ch&1 ready for everyone

        const uint32_t stb = sb + (uint32_t)(ch & 1) * STAGEB;
        const uint32_t aAh = stb, aAl = stb + TILEB;
        const uint32_t aBh = stb + 2 * TILEB, aBl = stb + 3 * TILEB;

#pragma unroll
        for (int ks = 0; ks < 2; ks++) {
            // B fragments once per k16-step (shared across all mt)
            uint32_t bh[2][4], bl[2][4];
            const int g = lane >> 3;
            const int brow = wn * 32 + ((g >> 1) << 3) + (lane & 7);
            const int bcol = ks * 16 + ((g & 1) << 3);
#pragma unroll
            for (int p = 0; p < 2; p++) {
                uint32_t o = (uint32_t)(((brow + p * 16) * GST + bcol) * 2);
                ldsm4(bh[p], aBh + o);
                ldsm4(bl[p], aBl + o);
            }
            const int arow = wm * 64 + (lane & 15);
            const int acol = ks * 16 + (lane >> 4) * 8;
            // A fragments per mt (keeps live regs ~100 for 2-CTA occupancy)
#pragma unroll
            for (int mt = 0; mt < 4; mt++) {
                uint32_t ah[4], al[4];
                uint32_t o = (uint32_t)(((arow + mt * 16) * GST + acol) * 2);
                ldsm4(ah, aAh + o);
                ldsm4(al, aAl + o);
#pragma unroll
                for (int p = 0; p < 2; p++) {
                    mma16816(acc[mt][2 * p],     ah, &bh[p][0]);
                    mma16816(acc[mt][2 * p],     ah, &bl[p][0]);
                    mma16816(acc[mt][2 * p],     al, &bh[p][0]);
                    mma16816(acc[mt][2 * p + 1], ah, &bh[p][2]);
                    mma16816(acc[mt][2 * p + 1], ah, &bl[p][2]);
                    mma16816(acc[mt][2 * p + 1], al, &bh[p][2]);
                }
            }
        }
        __syncthreads();            // stage ch&1 fully consumed
        if (ch + 2 < NCH) issue(ch + 2, ch & 1);
    }

    // epilogue
    const int g4 = lane >> 2, q2 = (lane & 3) * 2;
    if (MODE == 0) {
        __nv_bfloat16* oh = (z == 0) ? g_Qh : (z == 1) ? g_Kh : g_Vh;
        __nv_bfloat16* ol = (z == 0) ? g_Ql : (z == 1) ? g_Kl : g_Vl;
#pragma unroll
        for (int mt = 0; mt < 4; mt++)
#pragma unroll
            for (int nt = 0; nt < 4; nt++) {
                int r0 = m0 + wm * 64 + mt * 16 + g4;
                int n  = n0 + wn * 32 + nt * 8 + q2;
                int b = r0 >> 11, s = r0 & 2047;
                int h = n >> 6,  d = n & 63;
                size_t i0 = (((size_t)(b * Hh + h)) * Ss + s) * HD + d;
                size_t i1 = i0 + (size_t)8 * HD;
                uint32_t hh, ll;
                split2(acc[mt][nt][0], acc[mt][nt][1], hh, ll);
                *(uint32_t*)&oh[i0] = hh; *(uint32_t*)&ol[i0] = ll;
                split2(acc[mt][nt][2], acc[mt][nt][3], hh, ll);
                *(uint32_t*)&oh[i1] = hh; *(uint32_t*)&ol[i1] = ll;
            }
    } else {
#pragma unroll
        for (int mt = 0; mt < 4; mt++)
#pragma unroll
            for (int nt = 0; nt < 4; nt++) {
                int r0 = m0 + wm * 64 + mt * 16 + g4;
                int n  = n0 + wn * 32 + nt * 8 + q2;
                float b0 = bias[n], b1 = bias[n + 1];
                float2 v0 = {acc[mt][nt][0] + b0, acc[mt][nt][1] + b1};
                float2 v1 = {acc[mt][nt][2] + b0, acc[mt][nt][3] + b1};
                *(float2*)&outd[(size_t)r0 * Dd + n] = v0;
                *(float2*)&outd[(size_t)(r0 + 8) * Dd + n] = v1;
            }
    }
}

// ---------------------------------------------------------------------------
// 3) tensor-core causal flash attention, cp.async double-buffered K/V.
// Block = 128 thr (4 warps), q-tile 64, k-tile 64, HD = 64.
// ---------------------------------------------------------------------------
constexpr int FST  = 72;              // bf16 row stride
constexpr int FARR = 64 * FST * 2;    // 9216 B per array
// layout: [Qh, Ql, st0:{Kh,Kl,Vh,Vl}, st1:{Kh,Kl,Vh,Vl}]
constexpr int FLASH_SMEM = 10 * FARR; // 92160 B -> 2 CTAs/SM

__global__ __launch_bounds__(128) void flash_tc()
{
    extern __shared__ char fsc[];
    __nv_bfloat16* fs = (__nv_bfloat16*)fsc;
    const uint32_t sb = smaddr(fsc);

    const int tid = threadIdx.x, lane = tid & 31, wid = tid >> 5;
    const int qt = blockIdx.x, bhi = blockIdx.y;
    const size_t base = (size_t)bhi * Ss * HD;
    const float SCL = 0.125f * 1.4426950408889634f;  // 1/sqrt(HD) * log2(e)

    const __nv_bfloat16* ksrc[4] = {g_Kh + base, g_Kl + base, g_Vh + base, g_Vl + base};

    // issue one K/V stage: 16 x 16B cp.async per thread (4 per array)
    auto issue_kv = [&](int kt, int st) {
        const uint32_t stb = sb + (2 + st * 4) * FARR;
#pragma unroll
        for (int j = 0; j < 16; j++) {
            int arr = j >> 2;
            int c   = (j & 3) * 128 + tid;     // 0..511
            int row = c >> 3;                  // 0..63
            int c8  = (c & 7) * 8;             // bf16 col
            uint32_t dst = stb + arr * FARR + (uint32_t)(row * FST + c8) * 2;
            cp16(dst, ksrc[arr] + (size_t)(kt * 64 + row) * HD + c8);
        }
        CP_COMMIT();
    };

    issue_kv(0, 0);

    // load Q tile (plain loads; overlap with cp.async in flight)
    __nv_bfloat16* sQh = fs;
    __nv_bfloat16* sQl = fs + 64 * FST;
#pragma unroll
    for (int j = 0; j < 8; j++) {
        int row = (tid >> 4) + 8 * j;
        int c4  = (tid & 15) * 4;
        size_t go = base + (size_t)(qt * 64 + row) * HD + c4;
        *(uint2*)&sQh[row * FST + c4] = *(const uint2*)&g_Qh[go];
        *(uint2*)&sQl[row * FST + c4] = *(const uint2*)&g_Ql[go];
    }

    float m0_ = -1e30f, m1_ = -1e30f, l0_ = 0.f, l1_ = 0.f;
    float o[8][4];
#pragma unroll
    for (int t = 0; t < 8; t++)
#pragma unroll
        for (int c = 0; c < 4; c++) o[t][c] = 0.f;

    const uint32_t aQh = sb, aQl = sb + FARR;

    for (int kt = 0; kt <= qt; kt++) {
        if (kt < qt) { issue_kv(kt + 1, (kt + 1) & 1); CP_WAIT1(); }
        else         { CP_WAIT0(); }
        __syncthreads();

        const uint32_t stb = sb + (uint32_t)(2 + (kt & 1) * 4) * FARR;
        const uint32_t aKh = stb, aKl = stb + FARR;
        const uint32_t aVh = stb + 2 * FARR, aVl = stb + 3 * FARR;

        // S = Q K^T (3-term)
        float s[8][4];
#pragma unroll
        for (int t = 0; t < 8; t++)
#pragma unroll
            for (int c = 0; c < 4; c++) s[t][c] = 0.f;

#pragma unroll
        for (int ks = 0; ks < 4; ks++) {
            uint32_t qh[4], ql[4];
            const int arow = wid * 16 + (lane & 15);
            const int acol = ks * 16 + (lane >> 4) * 8;
            ldsm4(qh, aQh + (uint32_t)((arow * FST + acol) * 2));
            ldsm4(ql, aQl + (uint32_t)((arow * FST + acol) * 2));
            const int g = lane >> 3;
            const int br = ((g >> 1) << 3) + (lane & 7);
            const int bc = ks * 16 + ((g & 1) << 3);
#pragma unroll
            for (int p = 0; p < 4; p++) {
                uint32_t kh[4], kl[4];
                uint32_t off = (uint32_t)(((br + p * 16) * FST + bc) * 2);
                ldsm4(kh, aKh + off);
                ldsm4(kl, aKl + off);
                mma16816(s[2 * p],     qh, &kh[0]);
                mma16816(s[2 * p],     qh, &kl[0]);
                mma16816(s[2 * p],     ql, &kh[0]);
                mma16816(s[2 * p + 1], qh, &kh[2]);
                mma16816(s[2 * p + 1], qh, &kl[2]);
                mma16816(s[2 * p + 1], ql, &kh[2]);
            }
        }

        // scale (base-2) + causal mask + online softmax
        const int r0g = qt * 64 + wid * 16 + (lane >> 2);
        const int r1g = r0g + 8;
        const bool diag = (kt == qt);
        float mx0 = -1e30f, mx1 = -1e30f;
#pragma unroll
        for (int t = 0; t < 8; t++) {
            int cg = kt * 64 + t * 8 + (lane & 3) * 2;
            float v0 = s[t][0] * SCL, v1 = s[t][1] * SCL;
            float v2 = s[t][2] * SCL, v3 = s[t][3] * SCL;
            if (diag) {
                if (cg     > r0g) v0 = -1e30f;
                if (cg + 1 > r0g) v1 = -1e30f;
                if (cg     > r1g) v2 = -1e30f;
                if (cg + 1 > r1g) v3 = -1e30f;
            }
            s[t][0] = v0; s[t][1] = v1; s[t][2] = v2; s[t][3] = v3;
            mx0 = fmaxf(mx0, fmaxf(v0, v1));
            mx1 = fmaxf(mx1, fmaxf(v2, v3));
        }
        mx0 = fmaxf(mx0, __shfl_xor_sync(0xffffffffu, mx0, 1));
        mx0 = fmaxf(mx0, __shfl_xor_sync(0xffffffffu, mx0, 2));
        mx1 = fmaxf(mx1, __shfl_xor_sync(0xffffffffu, mx1, 1));
        mx1 = fmaxf(mx1, __shfl_xor_sync(0xffffffffu, mx1, 2));
        float nm0 = fmaxf(m0_, mx0), nm1 = fmaxf(m1_, mx1);
        float al0 = ex2f(m0_ - nm0), al1 = ex2f(m1_ - nm1);
        float sum0 = 0.f, sum1 = 0.f;
#pragma unroll
        for (int t = 0; t < 8; t++) {
            float p0 = ex2f(s[t][0] - nm0), p1 = ex2f(s[t][1] - nm0);
            float p2 = ex2f(s[t][2] - nm1), p3 = ex2f(s[t][3] - nm1);
            s[t][0] = p0; s[t][1] = p1; s[t][2] = p2; s[t][3] = p3;
            sum0 += p0 + p1; sum1 += p2 + p3;
        }
        sum0 += __shfl_xor_sync(0xffffffffu, sum0, 1);
        sum0 += __shfl_xor_sync(0xffffffffu, sum0, 2);
        sum1 += __shfl_xor_sync(0xffffffffu, sum1, 1);
        sum1 += __shfl_xor_sync(0xffffffffu, sum1, 2);
        l0_ = l0_ * al0 + sum0;
        l1_ = l1_ * al1 + sum1;
        m0_ = nm0; m1_ = nm1;
#pragma unroll
        for (int t = 0; t < 8; t++) {
            o[t][0] *= al0; o[t][1] *= al0;
            o[t][2] *= al1; o[t][3] *= al1;
        }

        // pack P into A-fragments (C-frag reuse), hi+lo
        uint32_t pah[4][4], pal[4][4];
#pragma unroll
        for (int t = 0; t < 4; t++) {
            split2(s[2 * t][0],     s[2 * t][1],     pah[t][0], pal[t][0]);
            split2(s[2 * t][2],     s[2 * t][3],     pah[t][1], pal[t][1]);
            split2(s[2 * t + 1][0], s[2 * t + 1][1], pah[t][2], pal[t][2]);
            split2(s[2 * t + 1][2], s[2 * t + 1][3], pah[t][3], pal[t][3]);
        }

        // O += P V (3-term), V fragments via ldmatrix.trans
        const int g = lane >> 3;
        const int vr = ((g & 1) << 3) + (lane & 7);
        const int vc = (lane >= 16) ? 8 : 0;
#pragma unroll
        for (int t = 0; t < 4; t++) {
#pragma unroll
            for (int dp = 0; dp < 4; dp++) {
                uint32_t vh[4], vl[4];
                uint32_t off = (uint32_t)(((t * 16 + vr) * FST + dp * 16 + vc) * 2);
                ldsm4t(vh, aVh + off);
                ldsm4t(vl, aVl + off);
                mma16816(o[2 * dp],     pah[t], &vh[0]);
                mma16816(o[2 * dp],     pah[t], &vl[0]);
                mma16816(o[2 * dp],     pal[t], &vh[0]);
                mma16816(o[2 * dp + 1], pah[t], &vh[2]);
                mma16816(o[2 * dp + 1], pah[t], &vl[2]);
                mma16816(o[2 * dp + 1], pal[t], &vh[2]);
            }
        }
        __syncthreads();   // stage fully consumed before next prefetch overwrite
    }

    // epilogue: normalize, split to bf16 hi/lo ctx [B*S, D]
    const int b = bhi >> 4, h = bhi & 15;
    const float i0 = 1.f / l0_, i1 = 1.f / l1_;
    const int r0 = qt * 64 + wid * 16 + (lane >> 2);
    const size_t row0 = (size_t)(b * Ss + r0) * Dd;
    const size_t row1 = row0 + (size_t)8 * Dd;
#pragma unroll
    for (int dt = 0; dt < 8; dt++) {
        int d = h * 64 + dt * 8 + (lane & 3) * 2;
        uint32_t hh, ll;
        split2(o[dt][0] * i0, o[dt][1] * i0, hh, ll);
        *(uint32_t*)&g_ctxh[row0 + d] = hh;
        *(uint32_t*)&g_ctxl[row0 + d] = ll;
        split2(o[dt][2] * i1, o[dt][3] * i1, hh, ll);
        *(uint32_t*)&g_ctxh[row1 + d] = hh;
        *(uint32_t*)&g_ctxl[row1 + d] = ll;
    }
}

// ---------------------------------------------------------------------------
extern "C" void kernel_launch(void* const* d_in, const int* in_sizes, int n_in,
                              void* d_out, int out_size)
{
    const float* x  = (const float*)d_in[0];
    const float* Wq = (const float*)d_in[1];
    const float* Wk = (const float*)d_in[2];
    const float* Wv = (const float*)d_in[3];
    const float* Wo = (const float*)d_in[4];
    const float* bo = (const float*)d_in[5];
    float* out = (float*)d_out;

    cudaFuncSetAttribute(gemm_tc<0>, cudaFuncAttributeMaxDynamicSharedMemorySize,
                         GEMM_SMEM);
    cudaFuncSetAttribute(gemm_tc<1>, cudaFuncAttributeMaxDynamicSharedMemorySize,
                         GEMM_SMEM);
    cudaFuncSetAttribute(flash_tc, cudaFuncAttributeMaxDynamicSharedMemorySize,
                         FLASH_SMEM);

    // 1) split inputs to bf16 hi/lo
    convert_split<<<(Mm * Dd / 4 + 4 * Dd * Dd / 4 + 255) / 256, 256>>>(
        x, Wq, Wk, Wv, Wo);

    // 2) QKV projections
    gemm_tc<0><<<dim3(Dd / 128, Mm / 128, 3), 256, GEMM_SMEM>>>(nullptr, nullptr);

    // 3) causal flash attention
    flash_tc<<<dim3(Ss / 64, Bb * Hh), 128, FLASH_SMEM>>>();

    // 4) output projection + bias
    gemm_tc<1><<<dim3(Dd / 128, Mm / 128, 1), 256, GEMM_SMEM>>>(bo, out);
}

// round 7
// speedup vs baseline: 3.1273x; 1.0395x over previous
#include <cuda_runtime.h>
#include <cuda_bf16.h>
#include <cstdint>

constexpr int Bb = 2, Ss = 2048, Dd = 1024, Hh = 16, HD = 64;
constexpr int Mm = Bb * Ss;  // 4096

// bf16 hi/lo split scratch (allocation-free rule: __device__ globals)
__device__ __align__(256) __nv_bfloat16 g_xh[Mm * Dd],  g_xl[Mm * Dd];
__device__ __align__(256) __nv_bfloat16 g_Wh[4 * Dd * Dd], g_Wl[4 * Dd * Dd];
__device__ __align__(256) __nv_bfloat16 g_Qh[Mm * Dd],  g_Ql[Mm * Dd];   // [B,H,S,HD]
__device__ __align__(256) __nv_bfloat16 g_Kh[Mm * Dd],  g_Kl[Mm * Dd];
__device__ __align__(256) __nv_bfloat16 g_Vh[Mm * Dd],  g_Vl[Mm * Dd];
__device__ __align__(256) __nv_bfloat16 g_ctxh[Mm * Dd], g_ctxl[Mm * Dd]; // [B*S, D]

// ---------------------------------------------------------------------------
// helpers
// ---------------------------------------------------------------------------
__device__ __forceinline__ uint32_t smaddr(const void* p) {
    uint32_t a;
    asm("{ .reg .u64 t; cvta.to.shared.u64 t, %1; cvt.u32.u64 %0, t; }"
        : "=r"(a) : "l"(p));
    return a;
}
// SW128 swizzle for 128B rows: r = row, b = byte-in-row (0..127)
__device__ __forceinline__ uint32_t swz(int r, int b) {
    return (uint32_t)(r * 128 + (b ^ ((r & 7) << 4)));
}
__device__ __forceinline__ void ldsm4(uint32_t* r, uint32_t a) {
    asm volatile("ldmatrix.sync.aligned.m8n8.x4.shared.b16 {%0,%1,%2,%3}, [%4];"
                 : "=r"(r[0]), "=r"(r[1]), "=r"(r[2]), "=r"(r[3]) : "r"(a));
}
__device__ __forceinline__ void ldsm4t(uint32_t* r, uint32_t a) {
    asm volatile("ldmatrix.sync.aligned.m8n8.x4.trans.shared.b16 {%0,%1,%2,%3}, [%4];"
                 : "=r"(r[0]), "=r"(r[1]), "=r"(r[2]), "=r"(r[3]) : "r"(a));
}
__device__ __forceinline__ void mma16816(float* c, const uint32_t* a, const uint32_t* b) {
    asm volatile(
        "mma.sync.aligned.m16n8k16.row.col.f32.bf16.bf16.f32 "
        "{%0,%1,%2,%3}, {%4,%5,%6,%7}, {%8,%9}, {%0,%1,%2,%3};"
        : "+f"(c[0]), "+f"(c[1]), "+f"(c[2]), "+f"(c[3])
        : "r"(a[0]), "r"(a[1]), "r"(a[2]), "r"(a[3]), "r"(b[0]), "r"(b[1]));
}
__device__ __forceinline__ float ex2f(float x) {
    float y;
    asm("ex2.approx.ftz.f32 %0, %1;" : "=f"(y) : "f"(x));
    return y;
}
__device__ __forceinline__ void cp16(uint32_t dst, const void* src) {
    asm volatile("cp.async.cg.shared.global [%0], [%1], 16;" :: "r"(dst), "l"(src));
}
#define CP_COMMIT() asm volatile("cp.async.commit_group;" ::: "memory")
#define CP_WAIT1()  asm volatile("cp.async.wait_group 1;" ::: "memory")
#define CP_WAIT0()  asm volatile("cp.async.wait_group 0;" ::: "memory")

// fp32 -> (bf16 hi, bf16 lo) for two values, packed as bf16x2 words
__device__ __forceinline__ void split2(float a, float b, uint32_t& h, uint32_t& l) {
    __nv_bfloat16 ha = __float2bfloat16(a);
    __nv_bfloat16 hb = __float2bfloat16(b);
    float ra = a - __bfloat162float(ha);
    float rb = b - __bfloat162float(hb);
    __nv_bfloat162 hv = __halves2bfloat162(ha, hb);
    __nv_bfloat162 lv = __floats2bfloat162_rn(ra, rb);
    h = *reinterpret_cast<uint32_t*>(&hv);
    l = *reinterpret_cast<uint32_t*>(&lv);
}

// ---------------------------------------------------------------------------
// 1) convert: split x and the 4 weight matrices into bf16 hi/lo
// ---------------------------------------------------------------------------
__global__ __launch_bounds__(256) void convert_split(const float* __restrict__ x,
                                                     const float* __restrict__ Wq,
                                                     const float* __restrict__ Wk,
                                                     const float* __restrict__ Wv,
                                                     const float* __restrict__ Wo)
{
    const int NX = Mm * Dd / 4;
    const int NW = Dd * Dd / 4;
    int i = blockIdx.x * 256 + threadIdx.x;
    if (i >= NX + 4 * NW) return;

    const float4* src;
    __nv_bfloat16 *dh, *dl;
    int off;
    if (i < NX) {
        src = (const float4*)x; dh = g_xh; dl = g_xl; off = i;
    } else {
        int j = i - NX;
        int w = j / NW;
        off = j % NW;
        const float* s = (w == 0) ? Wq : (w == 1) ? Wk : (w == 2) ? Wv : Wo;
        src = (const float4*)s;
        dh = g_Wh + (size_t)w * Dd * Dd;
        dl = g_Wl + (size_t)w * Dd * Dd;
    }
    float4 v = src[off];
    uint32_t h01, l01, h23, l23;
    split2(v.x, v.y, h01, l01);
    split2(v.z, v.w, h23, l23);
    uint2 hv = {h01, h23}, lv = {l01, l23};
    *(uint2*)&dh[(size_t)off * 4] = hv;
    *(uint2*)&dl[(size_t)off * 4] = lv;
}

// ---------------------------------------------------------------------------
// 2) GEMM v4: 128x128 block, 8 warps (64x32 warp tile), 3-stage cp.async,
//    ONE sync per chunk, swizzled 128B-row smem (hi|lo merged), 2 CTAs/SM.
//    smem per stage: sA 16KB + sB 16KB; rows: [hi k0..31 | lo k0..31]
// ---------------------------------------------------------------------------
constexpr int G_STAGE = 32768;             // bytes per stage (sA+sB)
constexpr int GEMM_SMEM = 3 * G_STAGE;     // 98304 B -> 2 CTAs/SM

template <int MODE>
__global__ __launch_bounds__(256, 2) void gemm_tc(const float* __restrict__ bias,
                                                  float* __restrict__ outd)
{
    extern __shared__ char smc[];
    const uint32_t sb = smaddr(smc);
    const int tid = threadIdx.x, lane = tid & 31, wid = tid >> 5;
    const int wm = wid & 1, wn = wid >> 1;           // warp grid 2m x 4n
    const int m0 = blockIdx.y * 128, n0 = blockIdx.x * 128;
    const int z = (MODE == 0) ? blockIdx.z : 3;

    const __nv_bfloat16* pAh = (MODE == 0) ? g_xh : g_ctxh;
    const __nv_bfloat16* pAl = (MODE == 0) ? g_xl : g_ctxl;
    const __nv_bfloat16* pBh = g_Wh + (size_t)z * Dd * Dd;
    const __nv_bfloat16* pBl = g_Wl + (size_t)z * Dd * Dd;

    // per-thread staging geometry: q = tid&7 (16B quad in row), rowsub = tid>>3
    const int q  = tid & 7;          // quads 0-3 = hi, 4-7 = lo
    const int rs = tid >> 3;         // 0..31
    const int kq = (q & 3) * 8;      // bf16 col offset within 32-chunk

    auto issue = [&](int ch, int st) {
        const int k0 = ch * 32 + kq;
        const uint32_t stb = sb + (uint32_t)st * G_STAGE;
#pragma unroll
        for (int j = 0; j < 4; j++) {          // sA rows
            int row = j * 32 + rs;
            const __nv_bfloat16* s = (q < 4 ? pAh : pAl) + (size_t)(m0 + row) * Dd + k0;
            cp16(stb + swz(row, q * 16), s);
        }
#pragma unroll
        for (int j = 0; j < 4; j++) {          // sB rows
            int row = j * 32 + rs;
            const __nv_bfloat16* s = (q < 4 ? pBh : pBl) + (size_t)(n0 + row) * Dd + k0;
            cp16(stb + 16384 + swz(row, q * 16), s);
        }
        CP_COMMIT();
    };

    float acc[4][4][4];
#pragma unroll
    for (int a = 0; a < 4; a++)
#pragma unroll
        for (int b = 0; b < 4; b++)
#pragma unroll
            for (int c = 0; c < 4; c++) acc[a][b][c] = 0.0f;

    issue(0, 0);
    issue(1, 1);

    constexpr int NCH = Dd / 32;   // 32
    for (int ch = 0; ch < NCH; ch++) {
        if (ch < NCH - 1) CP_WAIT1(); else CP_WAIT0();
        __syncthreads();                       // single barrier per chunk
        if (ch + 2 < NCH) issue(ch + 2, (ch + 2) % 3);

        const uint32_t aA = sb + (uint32_t)(ch % 3) * G_STAGE;
        const uint32_t aB = aA + 16384;

#pragma unroll
        for (int ks = 0; ks < 2; ks++) {
            // B fragments once per k16-step
            uint32_t bh[2][4], bl[2][4];
            const int g = lane >> 3;
            const int brow = wn * 32 + ((g >> 1) << 3) + (lane & 7);
            const int bqb = ks * 32 + ((g & 1) << 4);   // byte col (hi)
#pragma unroll
            for (int p = 0; p < 2; p++) {
                int r = brow + p * 16;
                ldsm4(bh[p], aB + swz(r, bqb));
                ldsm4(bl[p], aB + swz(r, bqb + 64));
            }
            const int arow = wm * 64 + (lane & 15);
            const int aqb = ks * 32 + ((lane >> 4) << 4);
#pragma unroll
            for (int mt = 0; mt < 4; mt++) {
                uint32_t ah[4], al[4];
                int r = arow + mt * 16;
                ldsm4(ah, aA + swz(r, aqb));
                ldsm4(al, aA + swz(r, aqb + 64));
#pragma unroll
                for (int p = 0; p < 2; p++) {
                    mma16816(acc[mt][2 * p],     ah, &bh[p][0]);
                    mma16816(acc[mt][2 * p],     ah, &bl[p][0]);
                    mma16816(acc[mt][2 * p],     al, &bh[p][0]);
                    mma16816(acc[mt][2 * p + 1], ah, &bh[p][2]);
                    mma16816(acc[mt][2 * p + 1], ah, &bl[p][2]);
                    mma16816(acc[mt][2 * p + 1], al, &bh[p][2]);
                }
            }
        }
    }

    // epilogue
    const int g4 = lane >> 2, q2 = (lane & 3) * 2;
    if (MODE == 0) {
        __nv_bfloat16* oh = (z == 0) ? g_Qh : (z == 1) ? g_Kh : g_Vh;
        __nv_bfloat16* ol = (z == 0) ? g_Ql : (z == 1) ? g_Kl : g_Vl;
#pragma unroll
        for (int mt = 0; mt < 4; mt++)
#pragma unroll
            for (int nt = 0; nt < 4; nt++) {
                int r0 = m0 + wm * 64 + mt * 16 + g4;
                int n  = n0 + wn * 32 + nt * 8 + q2;
                int b = r0 >> 11, s = r0 & 2047;
                int h = n >> 6,  d = n & 63;
                size_t i0 = (((size_t)(b * Hh + h)) * Ss + s) * HD + d;
                size_t i1 = i0 + (size_t)8 * HD;
                uint32_t hh, ll;
                split2(acc[mt][nt][0], acc[mt][nt][1], hh, ll);
                *(uint32_t*)&oh[i0] = hh; *(uint32_t*)&ol[i0] = ll;
                split2(acc[mt][nt][2], acc[mt][nt][3], hh, ll);
                *(uint32_t*)&oh[i1] = hh; *(uint32_t*)&ol[i1] = ll;
            }
    } else {
#pragma unroll
        for (int mt = 0; mt < 4; mt++)
#pragma unroll
            for (int nt = 0; nt < 4; nt++) {
                int r0 = m0 + wm * 64 + mt * 16 + g4;
                int n  = n0 + wn * 32 + nt * 8 + q2;
                float b0 = bias[n], b1 = bias[n + 1];
                float2 v0 = {acc[mt][nt][0] + b0, acc[mt][nt][1] + b1};
                float2 v1 = {acc[mt][nt][2] + b0, acc[mt][nt][3] + b1};
                *(float2*)&outd[(size_t)r0 * Dd + n] = v0;
                *(float2*)&outd[(size_t)(r0 + 8) * Dd + n] = v1;
            }
    }
}

// ---------------------------------------------------------------------------
// 3) flash v3: q-tile 128 (256 thr, 8 warps, 16 q-rows/warp), k-tile 64,
//    swizzled 128B-row smem, 2-stage cp.async K/V, 2 CTAs/SM (16 warps).
// smem: Qh 16K, Ql 16K, 2 stages x {Kh,Kl,Vh,Vl} 8K each = 64K. total 96K.
// ---------------------------------------------------------------------------
constexpr int F_Q   = 16384;          // per Q array
constexpr int F_KV  = 8192;           // per K/V array
constexpr int FLASH_SMEM = 2 * F_Q + 8 * F_KV;   // 98304

__global__ __launch_bounds__(256, 2) void flash_tc()
{
    extern __shared__ char fsc[];
    const uint32_t sb = smaddr(fsc);

    const int tid = threadIdx.x, lane = tid & 31, wid = tid >> 5;
    const int qt = blockIdx.x, bhi = blockIdx.y;
    const size_t base = (size_t)bhi * Ss * HD;
    const float SCL = 0.125f * 1.4426950408889634f;  // 1/sqrt(HD) * log2(e)

    const __nv_bfloat16* ksrc[4] = {g_Kh + base, g_Kl + base, g_Vh + base, g_Vl + base};

    const int q  = tid & 7;          // quad in 128B row
    const int rs = tid >> 3;         // 0..31

    // one K/V stage: 4 arrays x 64 rows x 8 quads = 2048 quads; 8 per thread
    auto issue_kv = [&](int kt, int st) {
        const uint32_t stb = sb + 2 * F_Q + (uint32_t)st * 4 * F_KV;
#pragma unroll
        for (int a = 0; a < 4; a++) {
#pragma unroll
            for (int j = 0; j < 2; j++) {
                int row = j * 32 + rs;
                cp16(stb + (uint32_t)a * F_KV + swz(row, q * 16),
                     ksrc[a] + (size_t)(kt * 64 + row) * HD + q * 8);
            }
        }
        CP_COMMIT();
    };

    const int ktmax = 2 * qt + 1;
    issue_kv(0, 0);

    // Q tile: 128 rows x 64 bf16, hi+lo (plain loads, swizzled stores)
#pragma unroll
    for (int j = 0; j < 4; j++) {
        int row = j * 32 + rs;
        size_t go = base + (size_t)(qt * 128 + row) * HD + q * 8;
        *(uint4*)(fsc + swz(row, q * 16))       = *(const uint4*)&g_Qh[go];
        *(uint4*)(fsc + F_Q + swz(row, q * 16)) = *(const uint4*)&g_Ql[go];
    }

    float m0_ = -1e30f, m1_ = -1e30f, l0_ = 0.f, l1_ = 0.f;
    float o[8][4];
#pragma unroll
    for (int t = 0; t < 8; t++)
#pragma unroll
        for (int c = 0; c < 4; c++) o[t][c] = 0.f;

    const uint32_t aQh = sb, aQl = sb + F_Q;

    for (int kt = 0; kt <= ktmax; kt++) {
        if (kt < ktmax) { issue_kv(kt + 1, (kt + 1) & 1); CP_WAIT1(); }
        else            { CP_WAIT0(); }
        __syncthreads();

        const uint32_t stb = sb + 2 * F_Q + (uint32_t)(kt & 1) * 4 * F_KV;
        const uint32_t aKh = stb, aKl = stb + F_KV;
        const uint32_t aVh = stb + 2 * F_KV, aVl = stb + 3 * F_KV;

        // S = Q K^T (3-term)
        float s[8][4];
#pragma unroll
        for (int t = 0; t < 8; t++)
#pragma unroll
            for (int c = 0; c < 4; c++) s[t][c] = 0.f;

#pragma unroll
        for (int ks = 0; ks < 4; ks++) {
            uint32_t qh[4], ql[4];
            const int arow = wid * 16 + (lane & 15);
            const int aqb  = ks * 32 + ((lane >> 4) << 4);
            ldsm4(qh, aQh + swz(arow, aqb));
            ldsm4(ql, aQl + swz(arow, aqb));
            const int g = lane >> 3;
            const int br = ((g >> 1) << 3) + (lane & 7);
            const int bqb = ks * 32 + ((g & 1) << 4);
#pragma unroll
            for (int p = 0; p < 4; p++) {
                uint32_t kh[4], kl[4];
                int r = br + p * 16;
                ldsm4(kh, aKh + swz(r, bqb));
                ldsm4(kl, aKl + swz(r, bqb));
                mma16816(s[2 * p],     qh, &kh[0]);
                mma16816(s[2 * p],     qh, &kl[0]);
                mma16816(s[2 * p],     ql, &kh[0]);
                mma16816(s[2 * p + 1], qh, &kh[2]);
                mma16816(s[2 * p + 1], qh, &kl[2]);
                mma16816(s[2 * p + 1], ql, &kh[2]);
            }
        }

        // scale (base-2) + causal mask (only needed on last two k-tiles)
        const int r0g = qt * 128 + wid * 16 + (lane >> 2);
        const int r1g = r0g + 8;
        const bool needmask = (kt >= 2 * qt);
        float mx0 = -1e30f, mx1 = -1e30f;
#pragma unroll
        for (int t = 0; t < 8; t++) {
            int cg = kt * 64 + t * 8 + (lane & 3) * 2;
            float v0 = s[t][0] * SCL, v1 = s[t][1] * SCL;
            float v2 = s[t][2] * SCL, v3 = s[t][3] * SCL;
            if (needmask) {
                if (cg     > r0g) v0 = -1e30f;
                if (cg + 1 > r0g) v1 = -1e30f;
                if (cg     > r1g) v2 = -1e30f;
                if (cg + 1 > r1g) v3 = -1e30f;
            }
            s[t][0] = v0; s[t][1] = v1; s[t][2] = v2; s[t][3] = v3;
            mx0 = fmaxf(mx0, fmaxf(v0, v1));
            mx1 = fmaxf(mx1, fmaxf(v2, v3));
        }
        mx0 = fmaxf(mx0, __shfl_xor_sync(0xffffffffu, mx0, 1));
        mx0 = fmaxf(mx0, __shfl_xor_sync(0xffffffffu, mx0, 2));
        mx1 = fmaxf(mx1, __shfl_xor_sync(0xffffffffu, mx1, 1));
        mx1 = fmaxf(mx1, __shfl_xor_sync(0xffffffffu, mx1, 2));
        float nm0 = fmaxf(m0_, mx0), nm1 = fmaxf(m1_, mx1);
        float al0 = ex2f(m0_ - nm0), al1 = ex2f(m1_ - nm1);
        float sum0 = 0.f, sum1 = 0.f;
#pragma unroll
        for (int t = 0; t < 8; t++) {
            float p0 = ex2f(s[t][0] - nm0), p1 = ex2f(s[t][1] - nm0);
            float p2 = ex2f(s[t][2] - nm1), p3 = ex2f(s[t][3] - nm1);
            s[t][0] = p0; s[t][1] = p1; s[t][2] = p2; s[t][3] = p3;
            sum0 += p0 + p1; sum1 += p2 + p3;
        }
        sum0 += __shfl_xor_sync(0xffffffffu, sum0, 1);
        sum0 += __shfl_xor_sync(0xffffffffu, sum0, 2);
        sum1 += __shfl_xor_sync(0xffffffffu, sum1, 1);
        sum1 += __shfl_xor_sync(0xffffffffu, sum1, 2);
        l0_ = l0_ * al0 + sum0;
        l1_ = l1_ * al1 + sum1;
        m0_ = nm0; m1_ = nm1;
#pragma unroll
        for (int t = 0; t < 8; t++) {
            o[t][0] *= al0; o[t][1] *= al0;
            o[t][2] *= al1; o[t][3] *= al1;
        }

        // pack P into A-fragments (C-frag reuse), hi+lo
        uint32_t pah[4][4], pal[4][4];
#pragma unroll
        for (int t = 0; t < 4; t++) {
            split2(s[2 * t][0],     s[2 * t][1],     pah[t][0], pal[t][0]);
            split2(s[2 * t][2],     s[2 * t][3],     pah[t][1], pal[t][1]);
            split2(s[2 * t + 1][0], s[2 * t + 1][1], pah[t][2], pal[t][2]);
            split2(s[2 * t + 1][2], s[2 * t + 1][3], pah[t][3], pal[t][3]);
        }

        // O += P V (3-term), V fragments via ldmatrix.trans
        const int g = lane >> 3;
        const int vr = ((g & 1) << 3) + (lane & 7);
        const int vcb = (lane >= 16) ? 16 : 0;   // byte col offset
#pragma unroll
        for (int t = 0; t < 4; t++) {
#pragma unroll
            for (int dp = 0; dp < 4; dp++) {
                uint32_t vh[4], vl[4];
                int r = t * 16 + vr;
                int b = dp * 32 + vcb;
                ldsm4t(vh, aVh + swz(r, b));
                ldsm4t(vl, aVl + swz(r, b));
                mma16816(o[2 * dp],     pah[t], &vh[0]);
                mma16816(o[2 * dp],     pah[t], &vl[0]);
                mma16816(o[2 * dp],     pal[t], &vh[0]);
                mma16816(o[2 * dp + 1], pah[t], &vh[2]);
                mma16816(o[2 * dp + 1], pah[t], &vl[2]);
                mma16816(o[2 * dp + 1], pal[t], &vh[2]);
            }
        }
        __syncthreads();   // stage fully consumed before next prefetch overwrite
    }

    // epilogue: normalize, split to bf16 hi/lo ctx [B*S, D]
    const int b = bhi >> 4, h = bhi & 15;
    const float i0 = 1.f / l0_, i1 = 1.f / l1_;
    const int r0 = qt * 128 + wid * 16 + (lane >> 2);
    const size_t row0 = (size_t)(b * Ss + r0) * Dd;
    const size_t row1 = row0 + (size_t)8 * Dd;
#pragma unroll
    for (int dt = 0; dt < 8; dt++) {
        int d = h * 64 + dt * 8 + (lane & 3) * 2;
        uint32_t hh, ll;
        split2(o[dt][0] * i0, o[dt][1] * i0, hh, ll);
        *(uint32_t*)&g_ctxh[row0 + d] = hh;
        *(uint32_t*)&g_ctxl[row0 + d] = ll;
        split2(o[dt][2] * i1, o[dt][3] * i1, hh, ll);
        *(uint32_t*)&g_ctxh[row1 + d] = hh;
        *(uint32_t*)&g_ctxl[row1 + d] = ll;
    }
}

// ---------------------------------------------------------------------------
extern "C" void kernel_launch(void* const* d_in, const int* in_sizes, int n_in,
                              void* d_out, int out_size)
{
    const float* x  = (const float*)d_in[0];
    const float* Wq = (const float*)d_in[1];
    const float* Wk = (const float*)d_in[2];
    const float* Wv = (const float*)d_in[3];
    const float* Wo = (const float*)d_in[4];
    const float* bo = (const float*)d_in[5];
    float* out = (float*)d_out;

    cudaFuncSetAttribute(gemm_tc<0>, cudaFuncAttributeMaxDynamicSharedMemorySize,
                         GEMM_SMEM);
    cudaFuncSetAttribute(gemm_tc<1>, cudaFuncAttributeMaxDynamicSharedMemorySize,
                         GEMM_SMEM);
    cudaFuncSetAttribute(flash_tc, cudaFuncAttributeMaxDynamicSharedMemorySize,
                         FLASH_SMEM);

    // 1) split inputs to bf16 hi/lo
    convert_split<<<(Mm * Dd / 4 + 4 * Dd * Dd / 4 + 255) / 256, 256>>>(
        x, Wq, Wk, Wv, Wo);

    // 2) QKV projections
    gemm_tc<0><<<dim3(Dd / 128, Mm / 128, 3), 256, GEMM_SMEM>>>(nullptr, nullptr);

    // 3) causal flash attention (q-tile 128)
    flash_tc<<<dim3(Ss / 128, Bb * Hh), 256, FLASH_SMEM>>>();

    // 4) output projection + bias
    gemm_tc<1><<<dim3(Dd / 128, Mm / 128, 1), 256, GEMM_SMEM>>>(bo, out);
}

// round 8
// speedup vs baseline: 4.5679x; 1.4606x over previous
#include <cuda_runtime.h>
#include <cuda_fp16.h>
#include <cstdint>

constexpr int Bb = 2, Ss = 2048, Dd = 1024, Hh = 16, HD = 64;
constexpr int Mm = Bb * Ss;  // 4096

// fp16 scratch (allocation-free rule: __device__ globals)
__device__ __align__(256) __half g_xh[Mm * Dd],  g_xl[Mm * Dd];   // x 2-term
__device__ __align__(256) __half g_W[4 * Dd * Dd];                // W single
__device__ __align__(256) __half g_Qh[Mm * Dd],  g_Ql[Mm * Dd];   // Q 2-term [B,H,S,HD]
__device__ __align__(256) __half g_Kh[Mm * Dd];                   // K single
__device__ __align__(256) __half g_Vh[Mm * Dd],  g_Vl[Mm * Dd];   // V 2-term
__device__ __align__(256) __half g_ctxh[Mm * Dd], g_ctxl[Mm * Dd]; // ctx 2-term [B*S,D]

// ---------------------------------------------------------------------------
// helpers
// ---------------------------------------------------------------------------
__device__ __forceinline__ uint32_t smaddr(const void* p) {
    uint32_t a;
    asm("{ .reg .u64 t; cvta.to.shared.u64 t, %1; cvt.u32.u64 %0, t; }"
        : "=r"(a) : "l"(p));
    return a;
}
// SW128 swizzle for 128B rows: r = row, b = byte-in-row (0..127)
__device__ __forceinline__ uint32_t swz(int r, int b) {
    return (uint32_t)(r * 128 + (b ^ ((r & 7) << 4)));
}
__device__ __forceinline__ void ldsm4(uint32_t* r, uint32_t a) {
    asm volatile("ldmatrix.sync.aligned.m8n8.x4.shared.b16 {%0,%1,%2,%3}, [%4];"
                 : "=r"(r[0]), "=r"(r[1]), "=r"(r[2]), "=r"(r[3]) : "r"(a));
}
__device__ __forceinline__ void ldsm4t(uint32_t* r, uint32_t a) {
    asm volatile("ldmatrix.sync.aligned.m8n8.x4.trans.shared.b16 {%0,%1,%2,%3}, [%4];"
                 : "=r"(r[0]), "=r"(r[1]), "=r"(r[2]), "=r"(r[3]) : "r"(a));
}
__device__ __forceinline__ void mma16816(float* c, const uint32_t* a, const uint32_t* b) {
    asm volatile(
        "mma.sync.aligned.m16n8k16.row.col.f32.f16.f16.f32 "
        "{%0,%1,%2,%3}, {%4,%5,%6,%7}, {%8,%9}, {%0,%1,%2,%3};"
        : "+f"(c[0]), "+f"(c[1]), "+f"(c[2]), "+f"(c[3])
        : "r"(a[0]), "r"(a[1]), "r"(a[2]), "r"(a[3]), "r"(b[0]), "r"(b[1]));
}
__device__ __forceinline__ float ex2f(float x) {
    float y;
    asm("ex2.approx.ftz.f32 %0, %1;" : "=f"(y) : "f"(x));
    return y;
}
__device__ __forceinline__ void cp16(uint32_t dst, const void* src) {
    asm volatile("cp.async.cg.shared.global [%0], [%1], 16;" :: "r"(dst), "l"(src));
}
#define CP_COMMIT() asm volatile("cp.async.commit_group;" ::: "memory")
#define CP_WAIT1()  asm volatile("cp.async.wait_group 1;" ::: "memory")
#define CP_WAIT0()  asm volatile("cp.async.wait_group 0;" ::: "memory")

// fp32 pair -> packed fp16x2 (first arg in low half)
__device__ __forceinline__ uint32_t pack2h(float a, float b) {
    __half2 v = __floats2half2_rn(a, b);
    return *reinterpret_cast<uint32_t*>(&v);
}
// fp32 pair -> (hi fp16x2, lo fp16x2) 2-term split
__device__ __forceinline__ void split2h(float a, float b, uint32_t& h, uint32_t& l) {
    __half2 hv = __floats2half2_rn(a, b);
    float2 hf = __half22float2(hv);
    __half2 lv = __floats2half2_rn(a - hf.x, b - hf.y);
    h = *reinterpret_cast<uint32_t*>(&hv);
    l = *reinterpret_cast<uint32_t*>(&lv);
}

// ---------------------------------------------------------------------------
// 1) convert: x -> fp16 2-term; W -> fp16 single
// ---------------------------------------------------------------------------
__global__ __launch_bounds__(256) void convert_split(const float* __restrict__ x,
                                                     const float* __restrict__ Wq,
                                                     const float* __restrict__ Wk,
                                                     const float* __restrict__ Wv,
                                                     const float* __restrict__ Wo)
{
    const int NX = Mm * Dd / 4;
    const int NW = Dd * Dd / 4;
    int i = blockIdx.x * 256 + threadIdx.x;
    if (i >= NX + 4 * NW) return;

    if (i < NX) {
        float4 v = ((const float4*)x)[i];
        uint32_t h01, l01, h23, l23;
        split2h(v.x, v.y, h01, l01);
        split2h(v.z, v.w, h23, l23);
        uint2 hv = {h01, h23}, lv = {l01, l23};
        *(uint2*)&g_xh[(size_t)i * 4] = hv;
        *(uint2*)&g_xl[(size_t)i * 4] = lv;
    } else {
        int j = i - NX;
        int w = j / NW;
        int off = j % NW;
        const float* s = (w == 0) ? Wq : (w == 1) ? Wk : (w == 2) ? Wv : Wo;
        float4 v = ((const float4*)s)[off];
        uint2 hv = {pack2h(v.x, v.y), pack2h(v.z, v.w)};
        *(uint2*)&g_W[(size_t)w * Dd * Dd + (size_t)off * 4] = hv;
    }
}

// ---------------------------------------------------------------------------
// 2) GEMM v5: 128x128 block, 8 warps (64x32 warp tile), 3-stage cp.async,
//    one sync per chunk, swizzled smem. A = 2-term fp16, B = single fp16.
//    Stage: sA 16KB (rows [hi 32k | lo 32k]) + sB 16KB (rows [hi 32k | unused]).
// ---------------------------------------------------------------------------
constexpr int G_STAGE = 32768;
constexpr int GEMM_SMEM = 3 * G_STAGE;     // 98304 B -> 2 CTAs/SM

template <int MODE>
__global__ __launch_bounds__(256, 2) void gemm_tc(const float* __restrict__ bias,
                                                  float* __restrict__ outd)
{
    extern __shared__ char smc[];
    const uint32_t sb = smaddr(smc);
    const int tid = threadIdx.x, lane = tid & 31, wid = tid >> 5;
    const int wm = wid & 1, wn = wid >> 1;           // warp grid 2m x 4n
    const int m0 = blockIdx.y * 128, n0 = blockIdx.x * 128;
    const int z = (MODE == 0) ? blockIdx.z : 3;

    const __half* pAh = (MODE == 0) ? g_xh : g_ctxh;
    const __half* pAl = (MODE == 0) ? g_xl : g_ctxl;
    const __half* pB  = g_W + (size_t)z * Dd * Dd;

    const int q  = tid & 7;          // 16B quad in 128B row; A: 0-3 hi, 4-7 lo
    const int rs = tid >> 3;         // 0..31
    const int kq = (q & 3) * 8;      // fp16 col offset in 32-chunk

    auto issue = [&](int ch, int st) {
        const int k0 = ch * 32 + kq;
        const uint32_t stb = sb + (uint32_t)st * G_STAGE;
#pragma unroll
        for (int j = 0; j < 4; j++) {          // sA rows (all 8 quads)
            int row = j * 32 + rs;
            const __half* s = (q < 4 ? pAh : pAl) + (size_t)(m0 + row) * Dd + k0;
            cp16(stb + swz(row, q * 16), s);
        }
        if (q < 4) {                            // sB rows (hi only)
#pragma unroll
            for (int j = 0; j < 4; j++) {
                int row = j * 32 + rs;
                cp16(stb + 16384 + swz(row, q * 16),
                     pB + (size_t)(n0 + row) * Dd + k0);
            }
        }
        CP_COMMIT();
    };

    float acc[4][4][4];
#pragma unroll
    for (int a = 0; a < 4; a++)
#pragma unroll
        for (int b = 0; b < 4; b++)
#pragma unroll
            for (int c = 0; c < 4; c++) acc[a][b][c] = 0.0f;

    issue(0, 0);
    issue(1, 1);

    constexpr int NCH = Dd / 32;   // 32
    for (int ch = 0; ch < NCH; ch++) {
        if (ch < NCH - 1) CP_WAIT1(); else CP_WAIT0();
        __syncthreads();
        if (ch + 2 < NCH) issue(ch + 2, (ch + 2) % 3);

        const uint32_t aA = sb + (uint32_t)(ch % 3) * G_STAGE;
        const uint32_t aB = aA + 16384;

#pragma unroll
        for (int ks = 0; ks < 2; ks++) {
            uint32_t bh[2][4];
            const int g = lane >> 3;
            const int brow = wn * 32 + ((g >> 1) << 3) + (lane & 7);
            const int bqb = ks * 32 + ((g & 1) << 4);
#pragma unroll
            for (int p = 0; p < 2; p++)
                ldsm4(bh[p], aB + swz(brow + p * 16, bqb));

            const int arow = wm * 64 + (lane & 15);
            const int aqb = ks * 32 + ((lane >> 4) << 4);
#pragma unroll
            for (int mt = 0; mt < 4; mt++) {
                uint32_t ah[4], al[4];
                int r = arow + mt * 16;
                ldsm4(ah, aA + swz(r, aqb));
                ldsm4(al, aA + swz(r, aqb + 64));
#pragma unroll
                for (int p = 0; p < 2; p++) {
                    mma16816(acc[mt][2 * p],     ah, &bh[p][0]);
                    mma16816(acc[mt][2 * p],     al, &bh[p][0]);
                    mma16816(acc[mt][2 * p + 1], ah, &bh[p][2]);
                    mma16816(acc[mt][2 * p + 1], al, &bh[p][2]);
                }
            }
        }
    }

    // epilogue
    const int g4 = lane >> 2, q2 = (lane & 3) * 2;
    if (MODE == 0) {
#pragma unroll
        for (int mt = 0; mt < 4; mt++)
#pragma unroll
            for (int nt = 0; nt < 4; nt++) {
                int r0 = m0 + wm * 64 + mt * 16 + g4;
                int n  = n0 + wn * 32 + nt * 8 + q2;
                int b = r0 >> 11, s = r0 & 2047;
                int h = n >> 6,  d = n & 63;
                size_t i0 = (((size_t)(b * Hh + h)) * Ss + s) * HD + d;
                size_t i1 = i0 + (size_t)8 * HD;
                if (z == 1) {   // K single fp16
                    *(uint32_t*)&g_Kh[i0] = pack2h(acc[mt][nt][0], acc[mt][nt][1]);
                    *(uint32_t*)&g_Kh[i1] = pack2h(acc[mt][nt][2], acc[mt][nt][3]);
                } else {        // Q or V: 2-term fp16
                    __half* oh = (z == 0) ? g_Qh : g_Vh;
                    __half* ol = (z == 0) ? g_Ql : g_Vl;
                    uint32_t hh, ll;
                    split2h(acc[mt][nt][0], acc[mt][nt][1], hh, ll);
                    *(uint32_t*)&oh[i0] = hh; *(uint32_t*)&ol[i0] = ll;
                    split2h(acc[mt][nt][2], acc[mt][nt][3], hh, ll);
                    *(uint32_t*)&oh[i1] = hh; *(uint32_t*)&ol[i1] = ll;
                }
            }
    } else {
#pragma unroll
        for (int mt = 0; mt < 4; mt++)
#pragma unroll
            for (int nt = 0; nt < 4; nt++) {
                int r0 = m0 + wm * 64 + mt * 16 + g4;
                int n  = n0 + wn * 32 + nt * 8 + q2;
                float b0 = bias[n], b1 = bias[n + 1];
                float2 v0 = {acc[mt][nt][0] + b0, acc[mt][nt][1] + b1};
                float2 v1 = {acc[mt][nt][2] + b0, acc[mt][nt][3] + b1};
                *(float2*)&outd[(size_t)r0 * Dd + n] = v0;
                *(float2*)&outd[(size_t)(r0 + 8) * Dd + n] = v1;
            }
    }
}

// ---------------------------------------------------------------------------
// 3) flash v4: q-tile 128 (256 thr, 8 warps), k-tile 64, fp16 2-term Q / V,
//    single K / P, swizzled smem, 2-stage cp.async, 2 CTAs/SM.
// smem: Qh 16K, Ql 16K, 2 stages x {Kh, Vh, Vl} 8K each = 48K. total 80K.
// ---------------------------------------------------------------------------
constexpr int F_Q   = 16384;
constexpr int F_KV  = 8192;
constexpr int FLASH_SMEM = 2 * F_Q + 6 * F_KV;   // 81920

__global__ __launch_bounds__(256, 2) void flash_tc()
{
    extern __shared__ char fsc[];
    const uint32_t sb = smaddr(fsc);

    const int tid = threadIdx.x, lane = tid & 31, wid = tid >> 5;
    const int qt = blockIdx.x, bhi = blockIdx.y;
    const size_t base = (size_t)bhi * Ss * HD;
    const float SCL = 0.125f * 1.4426950408889634f;  // 1/sqrt(HD) * log2(e)

    const __half* ksrc[3] = {g_Kh + base, g_Vh + base, g_Vl + base};

    const int q  = tid & 7;
    const int rs = tid >> 3;

    // one K/V stage: 3 arrays x 64 rows x 8 quads = 1536 quads; 6 per thread
    auto issue_kv = [&](int kt, int st) {
        const uint32_t stb = sb + 2 * F_Q + (uint32_t)st * 3 * F_KV;
#pragma unroll
        for (int a = 0; a < 3; a++) {
#pragma unroll
            for (int j = 0; j < 2; j++) {
                int row = j * 32 + rs;
                cp16(stb + (uint32_t)a * F_KV + swz(row, q * 16),
                     ksrc[a] + (size_t)(kt * 64 + row) * HD + q * 8);
            }
        }
        CP_COMMIT();
    };

    const int ktmax = 2 * qt + 1;
    issue_kv(0, 0);

    // Q tile: 128 rows x 64 fp16, hi+lo
#pragma unroll
    for (int j = 0; j < 4; j++) {
        int row = j * 32 + rs;
        size_t go = base + (size_t)(qt * 128 + row) * HD + q * 8;
        *(uint4*)(fsc + swz(row, q * 16))       = *(const uint4*)&g_Qh[go];
        *(uint4*)(fsc + F_Q + swz(row, q * 16)) = *(const uint4*)&g_Ql[go];
    }

    float m0_ = -1e30f, m1_ = -1e30f, l0_ = 0.f, l1_ = 0.f;
    float o[8][4];
#pragma unroll
    for (int t = 0; t < 8; t++)
#pragma unroll
        for (int c = 0; c < 4; c++) o[t][c] = 0.f;

    const uint32_t aQh = sb, aQl = sb + F_Q;

    for (int kt = 0; kt <= ktmax; kt++) {
        if (kt < ktmax) { issue_kv(kt + 1, (kt + 1) & 1); CP_WAIT1(); }
        else            { CP_WAIT0(); }
        __syncthreads();

        const uint32_t stb = sb + 2 * F_Q + (uint32_t)(kt & 1) * 3 * F_KV;
        const uint32_t aK  = stb;
        const uint32_t aVh = stb + F_KV, aVl = stb + 2 * F_KV;

        // S = Q K^T (2-term: Qh·K + Ql·K)
        float s[8][4];
#pragma unroll
        for (int t = 0; t < 8; t++)
#pragma unroll
            for (int c = 0; c < 4; c++) s[t][c] = 0.f;

#pragma unroll
        for (int ks = 0; ks < 4; ks++) {
            uint32_t qh[4], ql[4];
            const int arow = wid * 16 + (lane & 15);
            const int aqb  = ks * 32 + ((lane >> 4) << 4);
            ldsm4(qh, aQh + swz(arow, aqb));
            ldsm4(ql, aQl + swz(arow, aqb));
            const int g = lane >> 3;
            const int br = ((g >> 1) << 3) + (lane & 7);
            const int bqb = ks * 32 + ((g & 1) << 4);
#pragma unroll
            for (int p = 0; p < 4; p++) {
                uint32_t kh[4];
                ldsm4(kh, aK + swz(br + p * 16, bqb));
                mma16816(s[2 * p],     qh, &kh[0]);
                mma16816(s[2 * p],     ql, &kh[0]);
                mma16816(s[2 * p + 1], qh, &kh[2]);
                mma16816(s[2 * p + 1], ql, &kh[2]);
            }
        }

        // scale (base-2) + causal mask (last two k-tiles only)
        const int r0g = qt * 128 + wid * 16 + (lane >> 2);
        const int r1g = r0g + 8;
        const bool needmask = (kt >= 2 * qt);
        float mx0 = -1e30f, mx1 = -1e30f;
#pragma unroll
        for (int t = 0; t < 8; t++) {
            int cg = kt * 64 + t * 8 + (lane & 3) * 2;
            float v0 = s[t][0] * SCL, v1 = s[t][1] * SCL;
            float v2 = s[t][2] * SCL, v3 = s[t][3] * SCL;
            if (needmask) {
                if (cg     > r0g) v0 = -1e30f;
                if (cg + 1 > r0g) v1 = -1e30f;
                if (cg     > r1g) v2 = -1e30f;
                if (cg + 1 > r1g) v3 = -1e30f;
            }
            s[t][0] = v0; s[t][1] = v1; s[t][2] = v2; s[t][3] = v3;
            mx0 = fmaxf(mx0, fmaxf(v0, v1));
            mx1 = fmaxf(mx1, fmaxf(v2, v3));
        }
        mx0 = fmaxf(mx0, __shfl_xor_sync(0xffffffffu, mx0, 1));
        mx0 = fmaxf(mx0, __shfl_xor_sync(0xffffffffu, mx0, 2));
        mx1 = fmaxf(mx1, __shfl_xor_sync(0xffffffffu, mx1, 1));
        mx1 = fmaxf(mx1, __shfl_xor_sync(0xffffffffu, mx1, 2));
        float nm0 = fmaxf(m0_, mx0), nm1 = fmaxf(m1_, mx1);
        float al0 = ex2f(m0_ - nm0), al1 = ex2f(m1_ - nm1);
        float sum0 = 0.f, sum1 = 0.f;
#pragma unroll
        for (int t = 0; t < 8; t++) {
            float p0 = ex2f(s[t][0] - nm0), p1 = ex2f(s[t][1] - nm0);
            float p2 = ex2f(s[t][2] - nm1), p3 = ex2f(s[t][3] - nm1);
            s[t][0] = p0; s[t][1] = p1; s[t][2] = p2; s[t][3] = p3;
            sum0 += p0 + p1; sum1 += p2 + p3;
        }
        sum0 += __shfl_xor_sync(0xffffffffu, sum0, 1);
        sum0 += __shfl_xor_sync(0xffffffffu, sum0, 2);
        sum1 += __shfl_xor_sync(0xffffffffu, sum1, 1);
        sum1 += __shfl_xor_sync(0xffffffffu, sum1, 2);
        l0_ = l0_ * al0 + sum0;
        l1_ = l1_ * al1 + sum1;
        m0_ = nm0; m1_ = nm1;
#pragma unroll
        for (int t = 0; t < 8; t++) {
            o[t][0] *= al0; o[t][1] *= al0;
            o[t][2] *= al1; o[t][3] *= al1;
        }

        // pack P (single fp16) into A-fragments
        uint32_t pa[4][4];
#pragma unroll
        for (int t = 0; t < 4; t++) {
            pa[t][0] = pack2h(s[2 * t][0],     s[2 * t][1]);
            pa[t][1] = pack2h(s[2 * t][2],     s[2 * t][3]);
            pa[t][2] = pack2h(s[2 * t + 1][0], s[2 * t + 1][1]);
            pa[t][3] = pack2h(s[2 * t + 1][2], s[2 * t + 1][3]);
        }

        // O += P V (2-term: P·Vh + P·Vl), V via ldmatrix.trans
        const int g = lane >> 3;
        const int vr = ((g & 1) << 3) + (lane & 7);
        const int vcb = (lane >= 16) ? 16 : 0;
#pragma unroll
        for (int t = 0; t < 4; t++) {
#pragma unroll
            for (int dp = 0; dp < 4; dp++) {
                uint32_t vh[4], vl[4];
                int r = t * 16 + vr;
                int b = dp * 32 + vcb;
                ldsm4t(vh, aVh + swz(r, b));
                ldsm4t(vl, aVl + swz(r, b));
                mma16816(o[2 * dp],     pa[t], &vh[0]);
                mma16816(o[2 * dp],     pa[t], &vl[0]);
                mma16816(o[2 * dp + 1], pa[t], &vh[2]);
                mma16816(o[2 * dp + 1], pa[t], &vl[2]);
            }
        }
        __syncthreads();
    }

    // epilogue: normalize, 2-term fp16 ctx [B*S, D]
    const int b = bhi >> 4, h = bhi & 15;
    const float i0 = 1.f / l0_, i1 = 1.f / l1_;
    const int r0 = qt * 128 + wid * 16 + (lane >> 2);
    const size_t row0 = (size_t)(b * Ss + r0) * Dd;
    const size_t row1 = row0 + (size_t)8 * Dd;
#pragma unroll
    for (int dt = 0; dt < 8; dt++) {
        int d = h * 64 + dt * 8 + (lane & 3) * 2;
        uint32_t hh, ll;
        split2h(o[dt][0] * i0, o[dt][1] * i0, hh, ll);
        *(uint32_t*)&g_ctxh[row0 + d] = hh;
        *(uint32_t*)&g_ctxl[row0 + d] = ll;
        split2h(o[dt][2] * i1, o[dt][3] * i1, hh, ll);
        *(uint32_t*)&g_ctxh[row1 + d] = hh;
        *(uint32_t*)&g_ctxl[row1 + d] = ll;
    }
}

// ---------------------------------------------------------------------------
extern "C" void kernel_launch(void* const* d_in, const int* in_sizes, int n_in,
                              void* d_out, int out_size)
{
    const float* x  = (const float*)d_in[0];
    const float* Wq = (const float*)d_in[1];
    const float* Wk = (const float*)d_in[2];
    const float* Wv = (const float*)d_in[3];
    const float* Wo = (const float*)d_in[4];
    const float* bo = (const float*)d_in[5];
    float* out = (float*)d_out;

    cudaFuncSetAttribute(gemm_tc<0>, cudaFuncAttributeMaxDynamicSharedMemorySize,
                         GEMM_SMEM);
    cudaFuncSetAttribute(gemm_tc<1>, cudaFuncAttributeMaxDynamicSharedMemorySize,
                         GEMM_SMEM);
    cudaFuncSetAttribute(flash_tc, cudaFuncAttributeMaxDynamicSharedMemorySize,
                         FLASH_SMEM);

    // 1) x -> fp16 2-term; W -> fp16 single
    convert_split<<<(Mm * Dd / 4 + 4 * Dd * Dd / 4 + 255) / 256, 256>>>(
        x, Wq, Wk, Wv, Wo);

    // 2) QKV projections
    gemm_tc<0><<<dim3(Dd / 128, Mm / 128, 3), 256, GEMM_SMEM>>>(nullptr, nullptr);

    // 3) causal flash attention (q-tile 128)
    flash_tc<<<dim3(Ss / 128, Bb * Hh), 256, FLASH_SMEM>>>();

    // 4) output projection + bias
    gemm_tc<1><<<dim3(Dd / 128, Mm / 128, 1), 256, GEMM_SMEM>>>(bo, out);
}

// round 9
// speedup vs baseline: 4.8275x; 1.0568x over previous
#include <cuda_runtime.h>
#include <cuda_fp16.h>
#include <cstdint>

constexpr int Bb = 2, Ss = 2048, Dd = 1024, Hh = 16, HD = 64;
constexpr int Mm = Bb * Ss;  // 4096

// fp16 scratch (allocation-free rule: __device__ globals)
__device__ __align__(256) __half g_xh[Mm * Dd],  g_xl[Mm * Dd];   // x 2-term
__device__ __align__(256) __half g_W[4 * Dd * Dd];                // W single
__device__ __align__(256) __half g_Qh[Mm * Dd],  g_Ql[Mm * Dd];   // Q 2-term [B,H,S,HD]
__device__ __align__(256) __half g_Kh[Mm * Dd];                   // K single
__device__ __align__(256) __half g_Vh[Mm * Dd],  g_Vl[Mm * Dd];   // V 2-term
__device__ __align__(256) __half g_ctxh[Mm * Dd], g_ctxl[Mm * Dd]; // ctx 2-term [B*S,D]

// ---------------------------------------------------------------------------
// helpers
// ---------------------------------------------------------------------------
__device__ __forceinline__ uint32_t smaddr(const void* p) {
    uint32_t a;
    asm("{ .reg .u64 t; cvta.to.shared.u64 t, %1; cvt.u32.u64 %0, t; }"
        : "=r"(a) : "l"(p));
    return a;
}
// SW128 swizzle for 128B rows: r = row, b = byte-in-row (0..127)
__device__ __forceinline__ uint32_t swz(int r, int b) {
    return (uint32_t)(r * 128 + (b ^ ((r & 7) << 4)));
}
__device__ __forceinline__ void ldsm4(uint32_t* r, uint32_t a) {
    asm volatile("ldmatrix.sync.aligned.m8n8.x4.shared.b16 {%0,%1,%2,%3}, [%4];"
                 : "=r"(r[0]), "=r"(r[1]), "=r"(r[2]), "=r"(r[3]) : "r"(a));
}
__device__ __forceinline__ void ldsm4t(uint32_t* r, uint32_t a) {
    asm volatile("ldmatrix.sync.aligned.m8n8.x4.trans.shared.b16 {%0,%1,%2,%3}, [%4];"
                 : "=r"(r[0]), "=r"(r[1]), "=r"(r[2]), "=r"(r[3]) : "r"(a));
}
__device__ __forceinline__ void mma16816(float* c, const uint32_t* a, const uint32_t* b) {
    asm volatile(
        "mma.sync.aligned.m16n8k16.row.col.f32.f16.f16.f32 "
        "{%0,%1,%2,%3}, {%4,%5,%6,%7}, {%8,%9}, {%0,%1,%2,%3};"
        : "+f"(c[0]), "+f"(c[1]), "+f"(c[2]), "+f"(c[3])
        : "r"(a[0]), "r"(a[1]), "r"(a[2]), "r"(a[3]), "r"(b[0]), "r"(b[1]));
}
__device__ __forceinline__ float ex2f(float x) {
    float y;
    asm("ex2.approx.ftz.f32 %0, %1;" : "=f"(y) : "f"(x));
    return y;
}
__device__ __forceinline__ void cp16(uint32_t dst, const void* src) {
    asm volatile("cp.async.cg.shared.global [%0], [%1], 16;" :: "r"(dst), "l"(src));
}
#define CP_COMMIT() asm volatile("cp.async.commit_group;" ::: "memory")
#define CP_WAIT1()  asm volatile("cp.async.wait_group 1;" ::: "memory")
#define CP_WAIT0()  asm volatile("cp.async.wait_group 0;" ::: "memory")

// fp32 pair -> packed fp16x2 (first arg in low half)
__device__ __forceinline__ uint32_t pack2h(float a, float b) {
    __half2 v = __floats2half2_rn(a, b);
    return *reinterpret_cast<uint32_t*>(&v);
}
// fp32 pair -> (hi fp16x2, lo fp16x2) 2-term split
__device__ __forceinline__ void split2h(float a, float b, uint32_t& h, uint32_t& l) {
    __half2 hv = __floats2half2_rn(a, b);
    float2 hf = __half22float2(hv);
    __half2 lv = __floats2half2_rn(a - hf.x, b - hf.y);
    h = *reinterpret_cast<uint32_t*>(&hv);
    l = *reinterpret_cast<uint32_t*>(&lv);
}

// ---------------------------------------------------------------------------
// 1) convert: x -> fp16 2-term; W -> fp16 single
// ---------------------------------------------------------------------------
__global__ __launch_bounds__(256) void convert_split(const float* __restrict__ x,
                                                     const float* __restrict__ Wq,
                                                     const float* __restrict__ Wk,
                                                     const float* __restrict__ Wv,
                                                     const float* __restrict__ Wo)
{
    const int NX = Mm * Dd / 4;
    const int NW = Dd * Dd / 4;
    int i = blockIdx.x * 256 + threadIdx.x;
    if (i >= NX + 4 * NW) return;

    if (i < NX) {
        float4 v = ((const float4*)x)[i];
        uint32_t h01, l01, h23, l23;
        split2h(v.x, v.y, h01, l01);
        split2h(v.z, v.w, h23, l23);
        uint2 hv = {h01, h23}, lv = {l01, l23};
        *(uint2*)&g_xh[(size_t)i * 4] = hv;
        *(uint2*)&g_xl[(size_t)i * 4] = lv;
    } else {
        int j = i - NX;
        int w = j / NW;
        int off = j % NW;
        const float* s = (w == 0) ? Wq : (w == 1) ? Wk : (w == 2) ? Wv : Wo;
        float4 v = ((const float4*)s)[off];
        uint2 hv = {pack2h(v.x, v.y), pack2h(v.z, v.w)};
        *(uint2*)&g_W[(size_t)w * Dd * Dd + (size_t)off * 4] = hv;
    }
}

// ---------------------------------------------------------------------------
// 2) GEMM v6: 128x128 block, 8 warps (64x32 warp tile), K-chunk 64,
//    2-stage cp.async (48KB/stage, full 128B rows, zero waste), 2 CTAs/SM.
//    Stage layout: sAh 16K | sAl 16K | sB 16K.
// ---------------------------------------------------------------------------
constexpr int G_STAGE = 49152;
constexpr int GEMM_SMEM = 2 * G_STAGE;     // 98304 B -> 2 CTAs/SM

template <int MODE>
__global__ __launch_bounds__(256, 2) void gemm_tc(const float* __restrict__ bias,
                                                  float* __restrict__ outd)
{
    extern __shared__ char smc[];
    const uint32_t sb = smaddr(smc);
    const int tid = threadIdx.x, lane = tid & 31, wid = tid >> 5;
    const int wm = wid & 1, wn = wid >> 1;           // warp grid 2m x 4n
    const int m0 = blockIdx.y * 128, n0 = blockIdx.x * 128;
    const int z = (MODE == 0) ? blockIdx.z : 3;

    const __half* pAh = (MODE == 0) ? g_xh : g_ctxh;
    const __half* pAl = (MODE == 0) ? g_xl : g_ctxl;
    const __half* pB  = g_W + (size_t)z * Dd * Dd;

    const int q  = tid & 7;          // 16B quad in 128B row (k64 fp16)
    const int rs = tid >> 3;         // 0..31

    auto issue = [&](int ch, int st) {
        const int k0 = ch * 64 + q * 8;
        const uint32_t stb = sb + (uint32_t)st * G_STAGE;
#pragma unroll
        for (int j = 0; j < 4; j++) {
            int row = j * 32 + rs;
            uint32_t so = swz(row, q * 16);
            cp16(stb + so,         pAh + (size_t)(m0 + row) * Dd + k0);
            cp16(stb + 16384 + so, pAl + (size_t)(m0 + row) * Dd + k0);
            cp16(stb + 32768 + so, pB  + (size_t)(n0 + row) * Dd + k0);
        }
        CP_COMMIT();
    };

    float acc[4][4][4];
#pragma unroll
    for (int a = 0; a < 4; a++)
#pragma unroll
        for (int b = 0; b < 4; b++)
#pragma unroll
            for (int c = 0; c < 4; c++) acc[a][b][c] = 0.0f;

    issue(0, 0);
    issue(1, 1);

    constexpr int NCH = Dd / 64;   // 16
    for (int ch = 0; ch < NCH; ch++) {
        if (ch < NCH - 1) CP_WAIT1(); else CP_WAIT0();
        __syncthreads();

        const uint32_t aAh = sb + (uint32_t)(ch & 1) * G_STAGE;
        const uint32_t aAl = aAh + 16384;
        const uint32_t aB  = aAh + 32768;

#pragma unroll
        for (int ks = 0; ks < 4; ks++) {
            uint32_t bh[2][4];
            const int g = lane >> 3;
            const int brow = wn * 32 + ((g >> 1) << 3) + (lane & 7);
            const int bqb = ks * 32 + ((g & 1) << 4);
#pragma unroll
            for (int p = 0; p < 2; p++)
                ldsm4(bh[p], aB + swz(brow + p * 16, bqb));

            const int arow = wm * 64 + (lane & 15);
            const int aqb = ks * 32 + ((lane >> 4) << 4);
#pragma unroll
            for (int mt = 0; mt < 4; mt++) {
                uint32_t ah[4], al[4];
                int r = arow + mt * 16;
                ldsm4(ah, aAh + swz(r, aqb));
                ldsm4(al, aAl + swz(r, aqb));
#pragma unroll
                for (int p = 0; p < 2; p++) {
                    mma16816(acc[mt][2 * p],     ah, &bh[p][0]);
                    mma16816(acc[mt][2 * p],     al, &bh[p][0]);
                    mma16816(acc[mt][2 * p + 1], ah, &bh[p][2]);
                    mma16816(acc[mt][2 * p + 1], al, &bh[p][2]);
                }
            }
        }
        __syncthreads();
        if (ch + 2 < NCH) issue(ch + 2, ch & 1);
    }

    // epilogue
    const int g4 = lane >> 2, q2 = (lane & 3) * 2;
    if (MODE == 0) {
#pragma unroll
        for (int mt = 0; mt < 4; mt++)
#pragma unroll
            for (int nt = 0; nt < 4; nt++) {
                int r0 = m0 + wm * 64 + mt * 16 + g4;
                int n  = n0 + wn * 32 + nt * 8 + q2;
                int b = r0 >> 11, s = r0 & 2047;
                int h = n >> 6,  d = n & 63;
                size_t i0 = (((size_t)(b * Hh + h)) * Ss + s) * HD + d;
                size_t i1 = i0 + (size_t)8 * HD;
                if (z == 1) {   // K single fp16
                    *(uint32_t*)&g_Kh[i0] = pack2h(acc[mt][nt][0], acc[mt][nt][1]);
                    *(uint32_t*)&g_Kh[i1] = pack2h(acc[mt][nt][2], acc[mt][nt][3]);
                } else {        // Q or V: 2-term fp16
                    __half* oh = (z == 0) ? g_Qh : g_Vh;
                    __half* ol = (z == 0) ? g_Ql : g_Vl;
                    uint32_t hh, ll;
                    split2h(acc[mt][nt][0], acc[mt][nt][1], hh, ll);
                    *(uint32_t*)&oh[i0] = hh; *(uint32_t*)&ol[i0] = ll;
                    split2h(acc[mt][nt][2], acc[mt][nt][3], hh, ll);
                    *(uint32_t*)&oh[i1] = hh; *(uint32_t*)&ol[i1] = ll;
                }
            }
    } else {
#pragma unroll
        for (int mt = 0; mt < 4; mt++)
#pragma unroll
            for (int nt = 0; nt < 4; nt++) {
                int r0 = m0 + wm * 64 + mt * 16 + g4;
                int n  = n0 + wn * 32 + nt * 8 + q2;
                float b0 = bias[n], b1 = bias[n + 1];
                float2 v0 = {acc[mt][nt][0] + b0, acc[mt][nt][1] + b1};
                float2 v1 = {acc[mt][nt][2] + b0, acc[mt][nt][3] + b1};
                *(float2*)&outd[(size_t)r0 * Dd + n] = v0;
                *(float2*)&outd[(size_t)(r0 + 8) * Dd + n] = v1;
            }
    }
}

// ---------------------------------------------------------------------------
// 3) flash v5: q-tile 128 (256 thr, 8 warps), k-tile 64, fp16 2-term Q / V,
//    single K / P, swizzled smem, 2-stage cp.async, 2 CTAs/SM.
//    Heavy q-tiles scheduled FIRST (causal work ~ qt) for wave balance.
// smem: Qh 16K, Ql 16K, 2 stages x {Kh, Vh, Vl} 8K each = 48K. total 80K.
// ---------------------------------------------------------------------------
constexpr int F_Q   = 16384;
constexpr int F_KV  = 8192;
constexpr int FLASH_SMEM = 2 * F_Q + 6 * F_KV;   // 81920

__global__ __launch_bounds__(256, 2) void flash_tc()
{
    extern __shared__ char fsc[];
    const uint32_t sb = smaddr(fsc);

    const int tid = threadIdx.x, lane = tid & 31, wid = tid >> 5;
    const int qt = gridDim.x - 1 - blockIdx.x;     // heavy tiles first
    const int bhi = blockIdx.y;
    const size_t base = (size_t)bhi * Ss * HD;
    const float SCL = 0.125f * 1.4426950408889634f;  // 1/sqrt(HD) * log2(e)

    const __half* ksrc[3] = {g_Kh + base, g_Vh + base, g_Vl + base};

    const int q  = tid & 7;
    const int rs = tid >> 3;

    auto issue_kv = [&](int kt, int st) {
        const uint32_t stb = sb + 2 * F_Q + (uint32_t)st * 3 * F_KV;
#pragma unroll
        for (int a = 0; a < 3; a++) {
#pragma unroll
            for (int j = 0; j < 2; j++) {
                int row = j * 32 + rs;
                cp16(stb + (uint32_t)a * F_KV + swz(row, q * 16),
                     ksrc[a] + (size_t)(kt * 64 + row) * HD + q * 8);
            }
        }
        CP_COMMIT();
    };

    const int ktmax = 2 * qt + 1;
    issue_kv(0, 0);

    // Q tile: 128 rows x 64 fp16, hi+lo
#pragma unroll
    for (int j = 0; j < 4; j++) {
        int row = j * 32 + rs;
        size_t go = base + (size_t)(qt * 128 + row) * HD + q * 8;
        *(uint4*)(fsc + swz(row, q * 16))       = *(const uint4*)&g_Qh[go];
        *(uint4*)(fsc + F_Q + swz(row, q * 16)) = *(const uint4*)&g_Ql[go];
    }

    float m0_ = -1e30f, m1_ = -1e30f, l0_ = 0.f, l1_ = 0.f;
    float o[8][4];
#pragma unroll
    for (int t = 0; t < 8; t++)
#pragma unroll
        for (int c = 0; c < 4; c++) o[t][c] = 0.f;

    const uint32_t aQh = sb, aQl = sb + F_Q;

    for (int kt = 0; kt <= ktmax; kt++) {
        if (kt < ktmax) { issue_kv(kt + 1, (kt + 1) & 1); CP_WAIT1(); }
        else            { CP_WAIT0(); }
        __syncthreads();

        const uint32_t stb = sb + 2 * F_Q + (uint32_t)(kt & 1) * 3 * F_KV;
        const uint32_t aK  = stb;
        const uint32_t aVh = stb + F_KV, aVl = stb + 2 * F_KV;

        // S = Q K^T (2-term: Qh·K + Ql·K)
        float s[8][4];
#pragma unroll
        for (int t = 0; t < 8; t++)
#pragma unroll
            for (int c = 0; c < 4; c++) s[t][c] = 0.f;

#pragma unroll
        for (int ks = 0; ks < 4; ks++) {
            uint32_t qh[4], ql[4];
            const int arow = wid * 16 + (lane & 15);
            const int aqb  = ks * 32 + ((lane >> 4) << 4);
            ldsm4(qh, aQh + swz(arow, aqb));
            ldsm4(ql, aQl + swz(arow, aqb));
            const int g = lane >> 3;
            const int br = ((g >> 1) << 3) + (lane & 7);
            const int bqb = ks * 32 + ((g & 1) << 4);
#pragma unroll
            for (int p = 0; p < 4; p++) {
                uint32_t kh[4];
                ldsm4(kh, aK + swz(br + p * 16, bqb));
                mma16816(s[2 * p],     qh, &kh[0]);
                mma16816(s[2 * p],     ql, &kh[0]);
                mma16816(s[2 * p + 1], qh, &kh[2]);
                mma16816(s[2 * p + 1], ql, &kh[2]);
            }
        }

        // scale (base-2) + causal mask (last two k-tiles only)
        const int r0g = qt * 128 + wid * 16 + (lane >> 2);
        const int r1g = r0g + 8;
        const bool needmask = (kt >= 2 * qt);
        float mx0 = -1e30f, mx1 = -1e30f;
#pragma unroll
        for (int t = 0; t < 8; t++) {
            int cg = kt * 64 + t * 8 + (lane & 3) * 2;
            float v0 = s[t][0] * SCL, v1 = s[t][1] * SCL;
            float v2 = s[t][2] * SCL, v3 = s[t][3] * SCL;
            if (needmask) {
                if (cg     > r0g) v0 = -1e30f;
                if (cg + 1 > r0g) v1 = -1e30f;
                if (cg     > r1g) v2 = -1e30f;
                if (cg + 1 > r1g) v3 = -1e30f;
            }
            s[t][0] = v0; s[t][1] = v1; s[t][2] = v2; s[t][3] = v3;
            mx0 = fmaxf(mx0, fmaxf(v0, v1));
            mx1 = fmaxf(mx1, fmaxf(v2, v3));
        }
        mx0 = fmaxf(mx0, __shfl_xor_sync(0xffffffffu, mx0, 1));
        mx0 = fmaxf(mx0, __shfl_xor_sync(0xffffffffu, mx0, 2));
        mx1 = fmaxf(mx1, __shfl_xor_sync(0xffffffffu, mx1, 1));
        mx1 = fmaxf(mx1, __shfl_xor_sync(0xffffffffu, mx1, 2));
        float nm0 = fmaxf(m0_, mx0), nm1 = fmaxf(m1_, mx1);
        float al0 = ex2f(m0_ - nm0), al1 = ex2f(m1_ - nm1);
        float sum0 = 0.f, sum1 = 0.f;
#pragma unroll
        for (int t = 0; t < 8; t++) {
            float p0 = ex2f(s[t][0] - nm0), p1 = ex2f(s[t][1] - nm0);
            float p2 = ex2f(s[t][2] - nm1), p3 = ex2f(s[t][3] - nm1);
            s[t][0] = p0; s[t][1] = p1; s[t][2] = p2; s[t][3] = p3;
            sum0 += p0 + p1; sum1 += p2 + p3;
        }
        sum0 += __shfl_xor_sync(0xffffffffu, sum0, 1);
        sum0 += __shfl_xor_sync(0xffffffffu, sum0, 2);
        sum1 += __shfl_xor_sync(0xffffffffu, sum1, 1);
        sum1 += __shfl_xor_sync(0xffffffffu, sum1, 2);
        l0_ = l0_ * al0 + sum0;
        l1_ = l1_ * al1 + sum1;
        m0_ = nm0; m1_ = nm1;
#pragma unroll
        for (int t = 0; t < 8; t++) {
            o[t][0] *= al0; o[t][1] *= al0;
            o[t][2] *= al1; o[t][3] *= al1;
        }

        // pack P (single fp16) into A-fragments
        uint32_t pa[4][4];
#pragma unroll
        for (int t = 0; t < 4; t++) {
            pa[t][0] = pack2h(s[2 * t][0],     s[2 * t][1]);
            pa[t][1] = pack2h(s[2 * t][2],     s[2 * t][3]);
            pa[t][2] = pack2h(s[2 * t + 1][0], s[2 * t + 1][1]);
            pa[t][3] = pack2h(s[2 * t + 1][2], s[2 * t + 1][3]);
        }

        // O += P V (2-term: P·Vh + P·Vl), V via ldmatrix.trans
        const int g = lane >> 3;
        const int vr = ((g & 1) << 3) + (lane & 7);
        const int vcb = (lane >= 16) ? 16 : 0;
#pragma unroll
        for (int t = 0; t < 4; t++) {
#pragma unroll
            for (int dp = 0; dp < 4; dp++) {
                uint32_t vh[4], vl[4];
                int r = t * 16 + vr;
                int b = dp * 32 + vcb;
                ldsm4t(vh, aVh + swz(r, b));
                ldsm4t(vl, aVl + swz(r, b));
                mma16816(o[2 * dp],     pa[t], &vh[0]);
                mma16816(o[2 * dp],     pa[t], &vl[0]);
                mma16816(o[2 * dp + 1], pa[t], &vh[2]);
                mma16816(o[2 * dp + 1], pa[t], &vl[2]);
            }
        }
        __syncthreads();
    }

    // epilogue: normalize, 2-term fp16 ctx [B*S, D]
    const int b = bhi >> 4, h = bhi & 15;
    const float i0 = 1.f / l0_, i1 = 1.f / l1_;
    const int r0 = qt * 128 + wid * 16 + (lane >> 2);
    const size_t row0 = (size_t)(b * Ss + r0) * Dd;
    const size_t row1 = row0 + (size_t)8 * Dd;
#pragma unroll
    for (int dt = 0; dt < 8; dt++) {
        int d = h * 64 + dt * 8 + (lane & 3) * 2;
        uint32_t hh, ll;
        split2h(o[dt][0] * i0, o[dt][1] * i0, hh, ll);
        *(uint32_t*)&g_ctxh[row0 + d] = hh;
        *(uint32_t*)&g_ctxl[row0 + d] = ll;
        split2h(o[dt][2] * i1, o[dt][3] * i1, hh, ll);
        *(uint32_t*)&g_ctxh[row1 + d] = hh;
        *(uint32_t*)&g_ctxl[row1 + d] = ll;
    }
}

// ---------------------------------------------------------------------------
extern "C" void kernel_launch(void* const* d_in, const int* in_sizes, int n_in,
                              void* d_out, int out_size)
{
    const float* x  = (const float*)d_in[0];
    const float* Wq = (const float*)d_in[1];
    const float* Wk = (const float*)d_in[2];
    const float* Wv = (const float*)d_in[3];
    const float* Wo = (const float*)d_in[4];
    const float* bo = (const float*)d_in[5];
    float* out = (float*)d_out;

    cudaFuncSetAttribute(gemm_tc<0>, cudaFuncAttributeMaxDynamicSharedMemorySize,
                         GEMM_SMEM);
    cudaFuncSetAttribute(gemm_tc<1>, cudaFuncAttributeMaxDynamicSharedMemorySize,
                         GEMM_SMEM);
    cudaFuncSetAttribute(flash_tc, cudaFuncAttributeMaxDynamicSharedMemorySize,
                         FLASH_SMEM);

    // 1) x -> fp16 2-term; W -> fp16 single
    convert_split<<<(Mm * Dd / 4 + 4 * Dd * Dd / 4 + 255) / 256, 256>>>(
        x, Wq, Wk, Wv, Wo);

    // 2) QKV projections
    gemm_tc<0><<<dim3(Dd / 128, Mm / 128, 3), 256, GEMM_SMEM>>>(nullptr, nullptr);

    // 3) causal flash attention (q-tile 128, heavy-first)
    flash_tc<<<dim3(Ss / 128, Bb * Hh), 256, FLASH_SMEM>>>();

    // 4) output projection + bias
    gemm_tc<1><<<dim3(Dd / 128, Mm / 128, 1), 256, GEMM_SMEM>>>(bo, out);
}